// round 7
// baseline (speedup 1.0000x reference)
#include <cuda_runtime.h>
#include <math.h>
#include <float.h>

// Problem dims
#define BATCH 64
#define NN    10000
#define NC    201
#define H     64
#define ND    128      // node feature dim (2H)
#define HA    256      // actor/critic hidden
#define NB    9        // node partial blocks per batch
#define NPB   1112     // ceil(NN/NB)
#define TILE  32       // nodes per shared tile in featpool
#define CC    32       // candidates per actor block
#define NCHUNK 7       // ceil(201/32)
#define FS    36       // padded stride for feat rows (16B multiple)
#define MS    36

// Scratch (device globals: no allocation allowed)
__device__ float g_psum[BATCH][NB][ND];
__device__ float g_pmax[BATCH][NB][ND];
__device__ float g_pooled[BATCH][2 * ND];
__device__ float g_pproj[BATCH][HA];    // aw1-projection of pooled (const over candidates)
__device__ float g_scores[BATCH][NC];
__device__ int   g_mask_i32;

// ---- f32x2 packed helpers ----
static __device__ __forceinline__ unsigned long long dup2(float w) {
    unsigned long long r;
    unsigned int b = __float_as_uint(w);
    asm("mov.b64 %0, {%1, %1};" : "=l"(r) : "r"(b));
    return r;
}
static __device__ __forceinline__ unsigned long long fma2(
    unsigned long long a, unsigned long long b, unsigned long long c) {
    unsigned long long d;
    asm("fma.rn.f32x2 %0, %1, %2, %3;" : "=l"(d) : "l"(a), "l"(b), "l"(c));
    return d;
}
static __device__ __forceinline__ void unpack2(unsigned long long v, float& lo, float& hi) {
    unsigned int a, b;
    asm("mov.b64 {%0, %1}, %2;" : "=r"(a), "=r"(b) : "l"(v));
    lo = __uint_as_float(a);
    hi = __uint_as_float(b);
}

// ---------------------------------------------------------------------------
// K0: sniff mask dtype. int32 storage of 0/1 => bytes at offset%4!=0 all zero.
// ---------------------------------------------------------------------------
__global__ void k_sniff(const unsigned char* __restrict__ m) {
    if (threadIdx.x == 0) {
        int any = 0;
        for (int i = 0; i < 1024; i++)
            if ((i & 3) && m[i]) any = 1;
        g_mask_i32 = any ? 0 : 1;
    }
}

// ---------------------------------------------------------------------------
// K1: fused feature-extract + pooling partials (R5 version — proven).
// ---------------------------------------------------------------------------
__global__ __launch_bounds__(128) void k_featpool(
    const float* __restrict__ x,
    const float* __restrict__ w1, const float* __restrict__ b1,
    const float* __restrict__ w2, const float* __restrict__ b2)
{
    __shared__ __align__(16) float s_w1t[H][4];     // [k][w0,w1,w2,b1]
    __shared__ float s_x[TILE * 3];
    __shared__ __align__(16) float s_hT[H][TILE];   // hidden, transposed
    __shared__ __align__(16) float s_w2[H * ND];

    const int tid = threadIdx.x;
    const int b = blockIdx.y, nb = blockIdx.x;

    if (tid < H) {
        s_w1t[tid][0] = w1[tid];
        s_w1t[tid][1] = w1[H + tid];
        s_w1t[tid][2] = w1[2 * H + tid];
        s_w1t[tid][3] = b1[tid];
    }
    for (int i = tid; i < H * ND; i += 128) s_w2[i] = w2[i];

    const int n1 = tid & 31, kg = tid >> 5;
    const int dg = tid >> 1, ph = tid & 1;
    const int d0 = 2 * dg, d1 = d0 + 1;
    const float b20 = b2[d0], b21 = b2[d1];

    float sum0 = 0.f, sum1 = 0.f, max0 = 0.f, max1 = 0.f;  // relu >= 0
    const int start = nb * NPB;
    const int end = min(start + NPB, NN);

    for (int t = start; t < end; t += TILE) {
        const int cnt = min(TILE, end - t);
        if (tid < TILE * 3) {
            const int n = tid / 3, jj = tid - n * 3;
            s_x[tid] = (n < cnt) ? x[((long)b * NN + t + n) * 3 + jj] : 0.f;
        }
        __syncthreads();

        {
            const float x0 = s_x[n1 * 3 + 0];
            const float x1 = s_x[n1 * 3 + 1];
            const float x2 = s_x[n1 * 3 + 2];
#pragma unroll
            for (int m = 0; m < 16; m++) {
                const int k = kg * 16 + m;
                const float4 w = *(const float4*)&s_w1t[k][0];
                const float v = fmaf(x0, w.x, fmaf(x1, w.y, fmaf(x2, w.z, w.w)));
                s_hT[k][n1] = fmaxf(v, 0.f);
            }
        }
        __syncthreads();

        unsigned long long a2[16];
#pragma unroll
        for (int p = 0; p < 16; p++) a2[p] = 0ull;
#pragma unroll 4
        for (int k = 0; k < H; k++) {
            const float2 wp = *(const float2*)&s_w2[k * ND + d0];
            const unsigned long long w0 = dup2(wp.x);
            const unsigned long long w1d = dup2(wp.y);
            const ulonglong2* row = (const ulonglong2*)&s_hT[k][ph * 16];
#pragma unroll
            for (int q = 0; q < 4; q++) {
                const ulonglong2 h2 = row[q];
                a2[4 * q + 0] = fma2(h2.x, w0,  a2[4 * q + 0]);
                a2[4 * q + 1] = fma2(h2.x, w1d, a2[4 * q + 1]);
                a2[4 * q + 2] = fma2(h2.y, w0,  a2[4 * q + 2]);
                a2[4 * q + 3] = fma2(h2.y, w1d, a2[4 * q + 3]);
            }
        }
#pragma unroll
        for (int q = 0; q < 4; q++) {
            const int nb0 = ph * 16 + 4 * q;
            float lo, hi;
            unpack2(a2[4 * q + 0], lo, hi);
            if (nb0 < cnt)     { const float y = fmaxf(lo + b20, 0.f); sum0 += y; max0 = fmaxf(max0, y); }
            if (nb0 + 1 < cnt) { const float y = fmaxf(hi + b20, 0.f); sum0 += y; max0 = fmaxf(max0, y); }
            unpack2(a2[4 * q + 1], lo, hi);
            if (nb0 < cnt)     { const float y = fmaxf(lo + b21, 0.f); sum1 += y; max1 = fmaxf(max1, y); }
            if (nb0 + 1 < cnt) { const float y = fmaxf(hi + b21, 0.f); sum1 += y; max1 = fmaxf(max1, y); }
            unpack2(a2[4 * q + 2], lo, hi);
            if (nb0 + 2 < cnt) { const float y = fmaxf(lo + b20, 0.f); sum0 += y; max0 = fmaxf(max0, y); }
            if (nb0 + 3 < cnt) { const float y = fmaxf(hi + b20, 0.f); sum0 += y; max0 = fmaxf(max0, y); }
            unpack2(a2[4 * q + 3], lo, hi);
            if (nb0 + 2 < cnt) { const float y = fmaxf(lo + b21, 0.f); sum1 += y; max1 = fmaxf(max1, y); }
            if (nb0 + 3 < cnt) { const float y = fmaxf(hi + b21, 0.f); sum1 += y; max1 = fmaxf(max1, y); }
        }
    }

    __syncthreads();
    float* r = &s_hT[0][0];
    if (ph == 1) {
        r[dg] = sum0; r[64 + dg] = sum1;
        r[128 + dg] = max0; r[192 + dg] = max1;
    }
    __syncthreads();
    if (ph == 0) {
        sum0 += r[dg]; sum1 += r[64 + dg];
        max0 = fmaxf(max0, r[128 + dg]); max1 = fmaxf(max1, r[192 + dg]);
        g_psum[b][nb][d0] = sum0; g_psum[b][nb][d1] = sum1;
        g_pmax[b][nb][d0] = max0; g_pmax[b][nb][d1] = max1;
    }
}

// ---------------------------------------------------------------------------
// K1b: combine partials -> pooled; precompute aw1-projection of pooled.
// ---------------------------------------------------------------------------
__global__ __launch_bounds__(HA) void k_pool(const float* __restrict__ aw1) {
    __shared__ float s_pool[2 * ND];
    const int b = blockIdx.x, tid = threadIdx.x;
    if (tid < ND) {
        float s = 0.f, m = 0.f;
#pragma unroll
        for (int nb = 0; nb < NB; nb++) {
            s += g_psum[b][nb][tid];
            m = fmaxf(m, g_pmax[b][nb][tid]);
        }
        const float mean = s * (1.f / NN);
        g_pooled[b][tid] = mean;
        g_pooled[b][ND + tid] = m;
        s_pool[tid] = mean;
        s_pool[ND + tid] = m;
    }
    __syncthreads();
    float pc = 0.f;
    for (int i = 0; i < 2 * ND; i++)
        pc = fmaf(s_pool[i], __ldg(aw1 + (ND + i) * HA + tid), pc);
    g_pproj[b][tid] = pc;
}

// ---------------------------------------------------------------------------
// K2: actor, retiled. 128 threads; thread = (4 cands tc, 16 j's tr).
// Per k-step: 1 LDS.128 (A bcast) + 4 LDG.128 (weights, j-pairs load directly
// as f32x2, no pack) = 5 LSU (20cy) vs 32 FFMA2 (64cy) -> FMA-bound.
// ---------------------------------------------------------------------------
__global__ __launch_bounds__(128) void k_actor(
    const float* __restrict__ x, const int* __restrict__ cand,
    const float* __restrict__ fw1, const float* __restrict__ fb1,
    const float* __restrict__ fw2, const float* __restrict__ fb2,
    const float* __restrict__ aw1, const float* __restrict__ ab1,
    const float* __restrict__ aw2, const float* __restrict__ ab2,
    const float* __restrict__ aw3, const float* __restrict__ ab3)
{
    extern __shared__ float sm[];
    float* s_feat = sm;                      // ND*FS
    float* s_mid  = s_feat + ND * FS;        // HA*MS
    float* s_hT   = s_mid + HA * MS;         // H*CC
    float* s_x    = s_hT + H * CC;           // CC*3
    float* s_w1t  = s_x + CC * 3;            // H*4
    float* s_red  = s_w1t + H * 4;           // 128*4

    const int tid = threadIdx.x;
    const int b = blockIdx.y;
    const int c0 = blockIdx.x * CC;
    const int nvalid = min(CC, NC - c0);

    if (tid < H) {
        s_w1t[tid * 4 + 0] = fw1[tid];
        s_w1t[tid * 4 + 1] = fw1[H + tid];
        s_w1t[tid * 4 + 2] = fw1[2 * H + tid];
        s_w1t[tid * 4 + 3] = fb1[tid];
    }
    if (tid < CC * 3) {
        const int c = tid / 3, i = tid - c * 3;
        float v = 0.f;
        if (c < nvalid) {
            const int node = cand[b * NC + c0 + c];
            v = x[((long)b * NN + node) * 3 + i];
        }
        s_x[tid] = v;
    }
    __syncthreads();

    // fe layer 1 -> s_hT[k][c]
    {
        const int n1 = tid & 31, kg = tid >> 5;
        const float x0 = s_x[n1 * 3 + 0];
        const float x1 = s_x[n1 * 3 + 1];
        const float x2 = s_x[n1 * 3 + 2];
#pragma unroll
        for (int m = 0; m < 16; m++) {
            const int k = kg * 16 + m;
            const float4 w = *(const float4*)&s_w1t[k * 4];
            const float v = fmaf(x0, w.x, fmaf(x1, w.y, fmaf(x2, w.z, w.w)));
            s_hT[k * CC + n1] = fmaxf(v, 0.f);
        }
    }
    __syncthreads();

    // fe layer 2 -> s_feat[d][c]
    {
        const int dg = tid >> 1, ph = tid & 1;
        const int d0 = 2 * dg, d1 = d0 + 1;
        unsigned long long a2[16];
#pragma unroll
        for (int p = 0; p < 16; p++) a2[p] = 0ull;
#pragma unroll 4
        for (int k = 0; k < H; k++) {
            const float2 wp = __ldg((const float2*)(fw2 + k * ND + d0));
            const unsigned long long w0 = dup2(wp.x);
            const unsigned long long w1d = dup2(wp.y);
            const ulonglong2* row = (const ulonglong2*)(s_hT + k * CC + ph * 16);
#pragma unroll
            for (int q = 0; q < 4; q++) {
                const ulonglong2 h2 = row[q];
                a2[4 * q + 0] = fma2(h2.x, w0,  a2[4 * q + 0]);
                a2[4 * q + 1] = fma2(h2.x, w1d, a2[4 * q + 1]);
                a2[4 * q + 2] = fma2(h2.y, w0,  a2[4 * q + 2]);
                a2[4 * q + 3] = fma2(h2.y, w1d, a2[4 * q + 3]);
            }
        }
        const float b20 = fb2[d0], b21 = fb2[d1];
#pragma unroll
        for (int q = 0; q < 4; q++) {
            const int cb2_ = ph * 16 + 4 * q;
            float lo, hi;
            unpack2(a2[4 * q + 0], lo, hi);
            s_feat[d0 * FS + cb2_]     = fmaxf(lo + b20, 0.f);
            s_feat[d0 * FS + cb2_ + 1] = fmaxf(hi + b20, 0.f);
            unpack2(a2[4 * q + 1], lo, hi);
            s_feat[d1 * FS + cb2_]     = fmaxf(lo + b21, 0.f);
            s_feat[d1 * FS + cb2_ + 1] = fmaxf(hi + b21, 0.f);
            unpack2(a2[4 * q + 2], lo, hi);
            s_feat[d0 * FS + cb2_ + 2] = fmaxf(lo + b20, 0.f);
            s_feat[d0 * FS + cb2_ + 3] = fmaxf(hi + b20, 0.f);
            unpack2(a2[4 * q + 3], lo, hi);
            s_feat[d1 * FS + cb2_ + 2] = fmaxf(lo + b21, 0.f);
            s_feat[d1 * FS + cb2_ + 3] = fmaxf(hi + b21, 0.f);
        }
    }
    __syncthreads();

    // ---- actor tiling: thread = (tc: cands 4tc..4tc+3, tr: j 16tr..16tr+15)
    const int tc = tid & 7, tr = tid >> 3;
    const int cb = 4 * tc;
    const int jb = 16 * tr;

    unsigned long long acc[4][8];   // [cand][jpair]

    // ---- actor layer 1: k = 128 candidate-feature rows ----
#pragma unroll
    for (int c = 0; c < 4; c++)
#pragma unroll
        for (int jp = 0; jp < 8; jp++) acc[c][jp] = 0ull;

#pragma unroll 2
    for (int i = 0; i < ND; i++) {
        const float4 a4 = *(const float4*)(s_feat + i * FS + cb);
        const unsigned long long ad0 = dup2(a4.x), ad1 = dup2(a4.y);
        const unsigned long long ad2 = dup2(a4.z), ad3 = dup2(a4.w);
        const ulonglong2* wp = (const ulonglong2*)(aw1 + i * HA + jb);
        const ulonglong2 wA = __ldg(wp),     wB = __ldg(wp + 1);
        const ulonglong2 wC = __ldg(wp + 2), wD = __ldg(wp + 3);
        const unsigned long long wj[8] = {wA.x, wA.y, wB.x, wB.y,
                                          wC.x, wC.y, wD.x, wD.y};
#pragma unroll
        for (int jp = 0; jp < 8; jp++) {
            acc[0][jp] = fma2(wj[jp], ad0, acc[0][jp]);
            acc[1][jp] = fma2(wj[jp], ad1, acc[1][jp]);
            acc[2][jp] = fma2(wj[jp], ad2, acc[2][jp]);
            acc[3][jp] = fma2(wj[jp], ad3, acc[3][jp]);
        }
    }
    // epilogue: bias + pproj + tanh -> s_mid[j][c]
#pragma unroll
    for (int jp = 0; jp < 8; jp++) {
        const int j0 = jb + 2 * jp, j1 = j0 + 1;
        const float bb0 = ab1[j0] + g_pproj[b][j0];
        const float bb1 = ab1[j1] + g_pproj[b][j1];
        float lo0, hi0, lo1, hi1, lo2, hi2, lo3, hi3;
        unpack2(acc[0][jp], lo0, hi0);
        unpack2(acc[1][jp], lo1, hi1);
        unpack2(acc[2][jp], lo2, hi2);
        unpack2(acc[3][jp], lo3, hi3);
        *(float4*)(s_mid + j0 * MS + cb) = make_float4(
            tanhf(lo0 + bb0), tanhf(lo1 + bb0), tanhf(lo2 + bb0), tanhf(lo3 + bb0));
        *(float4*)(s_mid + j1 * MS + cb) = make_float4(
            tanhf(hi0 + bb1), tanhf(hi1 + bb1), tanhf(hi2 + bb1), tanhf(hi3 + bb1));
    }
    __syncthreads();

    // ---- actor layer 2: k = 256 rows of s_mid ----
#pragma unroll
    for (int c = 0; c < 4; c++)
#pragma unroll
        for (int jp = 0; jp < 8; jp++) acc[c][jp] = 0ull;

#pragma unroll 2
    for (int i = 0; i < HA; i++) {
        const float4 a4 = *(const float4*)(s_mid + i * MS + cb);
        const unsigned long long ad0 = dup2(a4.x), ad1 = dup2(a4.y);
        const unsigned long long ad2 = dup2(a4.z), ad3 = dup2(a4.w);
        const ulonglong2* wp = (const ulonglong2*)(aw2 + i * HA + jb);
        const ulonglong2 wA = __ldg(wp),     wB = __ldg(wp + 1);
        const ulonglong2 wC = __ldg(wp + 2), wD = __ldg(wp + 3);
        const unsigned long long wj[8] = {wA.x, wA.y, wB.x, wB.y,
                                          wC.x, wC.y, wD.x, wD.y};
#pragma unroll
        for (int jp = 0; jp < 8; jp++) {
            acc[0][jp] = fma2(wj[jp], ad0, acc[0][jp]);
            acc[1][jp] = fma2(wj[jp], ad1, acc[1][jp]);
            acc[2][jp] = fma2(wj[jp], ad2, acc[2][jp]);
            acc[3][jp] = fma2(wj[jp], ad3, acc[3][jp]);
        }
    }

    // ---- layer 3: per-thread partial over its 16 j, then cross-thread sum ----
    {
        float p0 = 0.f, p1 = 0.f, p2 = 0.f, p3 = 0.f;
#pragma unroll
        for (int jp = 0; jp < 8; jp++) {
            const int j0 = jb + 2 * jp, j1 = j0 + 1;
            const float bb0 = ab2[j0], bb1 = ab2[j1];
            const float w30 = aw3[j0], w31 = aw3[j1];
            float lo, hi;
            unpack2(acc[0][jp], lo, hi);
            p0 += tanhf(lo + bb0) * w30 + tanhf(hi + bb1) * w31;
            unpack2(acc[1][jp], lo, hi);
            p1 += tanhf(lo + bb0) * w30 + tanhf(hi + bb1) * w31;
            unpack2(acc[2][jp], lo, hi);
            p2 += tanhf(lo + bb0) * w30 + tanhf(hi + bb1) * w31;
            unpack2(acc[3][jp], lo, hi);
            p3 += tanhf(lo + bb0) * w30 + tanhf(hi + bb1) * w31;
        }
        *(float4*)(s_red + tid * 4) = make_float4(p0, p1, p2, p3);
    }
    __syncthreads();
    if (tid < CC) {
        const int tcc = tid >> 2, ccc = tid & 3;   // cand = 4*tcc + ccc = tid
        float s = ab3[0];
#pragma unroll
        for (int t = 0; t < 16; t++) s += s_red[(t * 8 + tcc) * 4 + ccc];
        if (tid < nvalid) g_scores[b][c0 + tid] = s;
    }
}

// ---------------------------------------------------------------------------
// K3: critic MLP on pooled feature + masked softmax over candidates.
// ---------------------------------------------------------------------------
__global__ __launch_bounds__(256) void k_final(
    const unsigned char* __restrict__ mask,
    const float* __restrict__ cw1, const float* __restrict__ cb1,
    const float* __restrict__ cw2, const float* __restrict__ cb2,
    const float* __restrict__ cw3, const float* __restrict__ cb3,
    float* __restrict__ out)
{
    __shared__ float s_in[HA];
    __shared__ float s_hid[HA];
    __shared__ float s_r[8];
    __shared__ float s_b0, s_b1v;

    const int tid = threadIdx.x, b = blockIdx.x;
    const int lane = tid & 31, warp = tid >> 5;

    s_in[tid] = g_pooled[b][tid];
    __syncthreads();
    float acc = cb1[tid];
    for (int i = 0; i < HA; i++) acc = fmaf(s_in[i], cw1[i * HA + tid], acc);
    s_hid[tid] = tanhf(acc);
    __syncthreads();
    acc = cb2[tid];
    for (int i = 0; i < HA; i++) acc = fmaf(s_hid[i], cw2[i * HA + tid], acc);
    {
        float p = tanhf(acc) * cw3[tid];
        p += __shfl_xor_sync(0xffffffffu, p, 16);
        p += __shfl_xor_sync(0xffffffffu, p, 8);
        p += __shfl_xor_sync(0xffffffffu, p, 4);
        p += __shfl_xor_sync(0xffffffffu, p, 2);
        p += __shfl_xor_sync(0xffffffffu, p, 1);
        if (lane == 0) s_r[warp] = p;
    }
    __syncthreads();
    if (tid == 0) {
        float v = cb3[0];
#pragma unroll
        for (int w = 0; w < 8; w++) v += s_r[w];
        out[BATCH * NC + b] = v;
    }

    const int c = tid;
    bool valid = false;
    float s = -FLT_MAX;
    if (c < NC) {
        const int mi = b * NC + c;
        const int mv = g_mask_i32 ? ((const int*)mask)[mi] : (int)mask[mi];
        valid = (mv != 0);
        if (valid) s = g_scores[b][c];
    }
    float m = s;
    m = fmaxf(m, __shfl_xor_sync(0xffffffffu, m, 16));
    m = fmaxf(m, __shfl_xor_sync(0xffffffffu, m, 8));
    m = fmaxf(m, __shfl_xor_sync(0xffffffffu, m, 4));
    m = fmaxf(m, __shfl_xor_sync(0xffffffffu, m, 2));
    m = fmaxf(m, __shfl_xor_sync(0xffffffffu, m, 1));
    __syncthreads();
    if (lane == 0) s_r[warp] = m;
    __syncthreads();
    if (warp == 0) {
        float t = (lane < 8) ? s_r[lane] : -FLT_MAX;
        t = fmaxf(t, __shfl_xor_sync(0xffffffffu, t, 4));
        t = fmaxf(t, __shfl_xor_sync(0xffffffffu, t, 2));
        t = fmaxf(t, __shfl_xor_sync(0xffffffffu, t, 1));
        if (lane == 0) s_b0 = t;
    }
    __syncthreads();
    const float mx = s_b0;
    const float e = valid ? expf(s - mx) : 0.f;
    float se = e;
    se += __shfl_xor_sync(0xffffffffu, se, 16);
    se += __shfl_xor_sync(0xffffffffu, se, 8);
    se += __shfl_xor_sync(0xffffffffu, se, 4);
    se += __shfl_xor_sync(0xffffffffu, se, 2);
    se += __shfl_xor_sync(0xffffffffu, se, 1);
    __syncthreads();
    if (lane == 0) s_r[warp] = se;
    __syncthreads();
    if (warp == 0) {
        float t = (lane < 8) ? s_r[lane] : 0.f;
        t += __shfl_xor_sync(0xffffffffu, t, 4);
        t += __shfl_xor_sync(0xffffffffu, t, 2);
        t += __shfl_xor_sync(0xffffffffu, t, 1);
        if (lane == 0) s_b1v = t;
    }
    __syncthreads();
    if (c < NC) out[b * NC + c] = e / s_b1v;
}

// ---------------------------------------------------------------------------
extern "C" void kernel_launch(void* const* d_in, const int* in_sizes, int n_in,
                              void* d_out, int out_size)
{
    const float* x    = (const float*)d_in[0];
    const int*   cand = (const int*)d_in[1];
    const unsigned char* mask = (const unsigned char*)d_in[2];
    const float* fw1 = (const float*)d_in[3];
    const float* fb1 = (const float*)d_in[4];
    const float* fw2 = (const float*)d_in[5];
    const float* fb2 = (const float*)d_in[6];
    const float* aw1 = (const float*)d_in[7];
    const float* ab1 = (const float*)d_in[8];
    const float* aw2 = (const float*)d_in[9];
    const float* ab2 = (const float*)d_in[10];
    const float* aw3 = (const float*)d_in[11];
    const float* ab3 = (const float*)d_in[12];
    const float* cw1 = (const float*)d_in[13];
    const float* cb1 = (const float*)d_in[14];
    const float* cw2 = (const float*)d_in[15];
    const float* cb2 = (const float*)d_in[16];
    const float* cw3 = (const float*)d_in[17];
    const float* cb3 = (const float*)d_in[18];
    float* out = (float*)d_out;

    const int smem_actor =
        (ND * FS + HA * MS + H * CC + CC * 3 + H * 4 + 128 * 4) * (int)sizeof(float);
    cudaFuncSetAttribute(k_actor, cudaFuncAttributeMaxDynamicSharedMemorySize,
                         smem_actor);

    k_sniff<<<1, 32>>>(mask);
    k_featpool<<<dim3(NB, BATCH), 128>>>(x, fw1, fb1, fw2, fb2);
    k_pool<<<BATCH, HA>>>(aw1);
    k_actor<<<dim3(NCHUNK, BATCH), 128, smem_actor>>>(
        x, cand, fw1, fb1, fw2, fb2, aw1, ab1, aw2, ab2, aw3, ab3);
    k_final<<<BATCH, 256>>>(mask, cw1, cb1, cw2, cb2, cw3, cb3, out);
}

// round 9
// speedup vs baseline: 1.2823x; 1.2823x over previous
#include <cuda_runtime.h>
#include <math.h>
#include <float.h>
#include <stdint.h>

// Problem dims
#define BATCH 64
#define NN    10000
#define NC    201
#define H     64
#define ND    128      // node feature dim (2H)
#define HA    256      // actor/critic hidden
#define NCH   6        // chunks per batch (wmma featpool)
#define TPT   13       // 128-node tiles per chunk (6*13*128 = 9984)
#define NTAIL 16       // tail nodes handled in k_pool
#define CC    32       // candidates per actor block
#define NCHUNK 7       // ceil(201/32)
#define FS    36
#define MS    36

// Scratch (device globals: no allocation allowed)
__device__ float g_psum[BATCH][NCH][ND];
__device__ float g_pmax[BATCH][NCH][ND];
__device__ float g_pooled[BATCH][2 * ND];
__device__ float g_pproj[BATCH][HA];
__device__ float g_scores[BATCH][NC];
__device__ int   g_mask_i32;

// ---- f32x2 packed helpers ----
static __device__ __forceinline__ unsigned long long dup2(float w) {
    unsigned long long r;
    unsigned int b = __float_as_uint(w);
    asm("mov.b64 %0, {%1, %1};" : "=l"(r) : "r"(b));
    return r;
}
static __device__ __forceinline__ unsigned long long fma2(
    unsigned long long a, unsigned long long b, unsigned long long c) {
    unsigned long long d;
    asm("fma.rn.f32x2 %0, %1, %2, %3;" : "=l"(d) : "l"(a), "l"(b), "l"(c));
    return d;
}
static __device__ __forceinline__ void unpack2(unsigned long long v, float& lo, float& hi) {
    unsigned int a, b;
    asm("mov.b64 {%0, %1}, %2;" : "=r"(a), "=r"(b) : "l"(v));
    lo = __uint_as_float(a);
    hi = __uint_as_float(b);
}

// ---- tf32 warp-MMA helpers (sm_80+ generic; compiles for compute_103 base) ----
static __device__ __forceinline__ uint32_t to_tf32(float f) {
    uint32_t r;
    asm("cvt.rna.tf32.f32 %0, %1;" : "=r"(r) : "f"(f));
    return r;
}
static __device__ __forceinline__ void split_tf32(float f, uint32_t& hi, uint32_t& lo) {
    hi = to_tf32(f);
    lo = to_tf32(f - __uint_as_float(hi));
}
static __device__ __forceinline__ void hmma_tf32(
    float* d, const uint4& a, uint32_t b0, uint32_t b1) {
    asm volatile(
        "mma.sync.aligned.m16n8k8.row.col.f32.tf32.tf32.f32 "
        "{%0,%1,%2,%3}, {%4,%5,%6,%7}, {%8,%9}, {%0,%1,%2,%3};"
        : "+f"(d[0]), "+f"(d[1]), "+f"(d[2]), "+f"(d[3])
        : "r"(a.x), "r"(a.y), "r"(a.z), "r"(a.w), "r"(b0), "r"(b1));
}

// ---------------------------------------------------------------------------
// K0: sniff mask dtype.
// ---------------------------------------------------------------------------
__global__ void k_sniff(const unsigned char* __restrict__ m) {
    if (threadIdx.x == 0) {
        int any = 0;
        for (int i = 0; i < 1024; i++)
            if ((i & 3) && m[i]) any = 1;
        g_mask_i32 = any ? 0 : 1;
    }
}

// ---------------------------------------------------------------------------
// K1: featpool via 3xTF32 warp MMA (error-compensated: AhBh + AhBl + AlBh).
// Block = 256 thr (8 warps). Warp w owns d-columns [16w, 16w+16) (2 n-tiles).
// A fragments (hi+lo) in dynamic smem; B fragments (hi+lo) register-resident.
// Fragment layout identical to R8 (validated: R8 error was pure tf32 rounding).
// ---------------------------------------------------------------------------
__global__ __launch_bounds__(256) void k_featpool_wmma(
    const float* __restrict__ x,
    const float* __restrict__ w1, const float* __restrict__ b1,
    const float* __restrict__ w2, const float* __restrict__ b2)
{
    extern __shared__ __align__(16) uint32_t s_dyn[];
    uint32_t* s_Ah = s_dyn;                 // 8*8*128 = 8192 u32 (32KB)
    uint32_t* s_Al = s_dyn + 8192;          // 32KB
    __shared__ __align__(16) float4 s_x4[128];
    __shared__ __align__(16) float s_w1t[H][4];

    const int tid = threadIdx.x;
    const int wid = tid >> 5, lane = tid & 31;
    const int b = blockIdx.y, chunk = blockIdx.x;
    const int base = chunk * TPT * 128;
    const int tig = lane & 3;        // thread-in-group (col group)
    const int gid = lane >> 2;       // group id (row group)

    if (tid < H) {
        s_w1t[tid][0] = w1[tid];
        s_w1t[tid][1] = w1[H + tid];
        s_w1t[tid][2] = w1[2 * H + tid];
        s_w1t[tid][3] = b1[tid];
    }

    // B fragments hi/lo: w2[k][d], k = kc*8 + tig (+4), d = 16*wid + nt*8 + gid
    uint32_t Bh[8][2][2], Bl[8][2][2];
#pragma unroll
    for (int kc = 0; kc < 8; kc++)
#pragma unroll
        for (int nt = 0; nt < 2; nt++) {
            const int k0 = kc * 8 + tig;
            const int d = 16 * wid + nt * 8 + gid;
            split_tf32(__ldg(w2 + k0 * ND + d),       Bh[kc][nt][0], Bl[kc][nt][0]);
            split_tf32(__ldg(w2 + (k0 + 4) * ND + d), Bh[kc][nt][1], Bl[kc][nt][1]);
        }

    float bcol[2][2];
#pragma unroll
    for (int nt = 0; nt < 2; nt++) {
        const int d0 = 16 * wid + nt * 8 + 2 * tig;
        bcol[nt][0] = b2[d0];
        bcol[nt][1] = b2[d0 + 1];
    }

    float psum[2][4], pmax[2][4];
#pragma unroll
    for (int nt = 0; nt < 2; nt++)
#pragma unroll
        for (int e = 0; e < 4; e++) { psum[nt][e] = 0.f; pmax[nt][e] = 0.f; }

    __syncthreads();

    for (int t = 0; t < TPT; t++) {
        if (tid < 128) {
            const int node = base + t * 128 + tid;
            const float* xp = x + ((long)b * NN + node) * 3;
            s_x4[tid] = make_float4(xp[0], xp[1], xp[2], 0.f);
        }
        __syncthreads();   // orders prev tile's A reads before new writes

        // layer-1 into A-fragment layout (hi + lo): 8 quads per thread
#pragma unroll
        for (int q = 0; q < 8; q++) {
            const int slot = q * 256 + tid;
            const int mt = slot >> 8;
            const int kc = (slot >> 5) & 7;
            const int ln = slot & 31;
            const int r = ln >> 2, c = ln & 3;
            const float4 xa = s_x4[mt * 16 + r];
            const float4 xb = s_x4[mt * 16 + r + 8];
            const float4 wA = *(const float4*)&s_w1t[kc * 8 + c][0];
            const float4 wB = *(const float4*)&s_w1t[kc * 8 + c + 4][0];
            const float h00 = fmaxf(fmaf(xa.x, wA.x, fmaf(xa.y, wA.y, fmaf(xa.z, wA.z, wA.w))), 0.f);
            const float h10 = fmaxf(fmaf(xb.x, wA.x, fmaf(xb.y, wA.y, fmaf(xb.z, wA.z, wA.w))), 0.f);
            const float h01 = fmaxf(fmaf(xa.x, wB.x, fmaf(xa.y, wB.y, fmaf(xa.z, wB.z, wB.w))), 0.f);
            const float h11 = fmaxf(fmaf(xb.x, wB.x, fmaf(xb.y, wB.y, fmaf(xb.z, wB.z, wB.w))), 0.f);
            uint4 vh, vl;
            split_tf32(h00, vh.x, vl.x);
            split_tf32(h10, vh.y, vl.y);
            split_tf32(h01, vh.z, vl.z);
            split_tf32(h11, vh.w, vl.w);
            const int off = (mt * 8 + kc) * 128 + ln * 4;
            *(uint4*)&s_Ah[off] = vh;
            *(uint4*)&s_Al[off] = vl;
        }
        __syncthreads();

        // MMA (3xTF32) + fragment-wise pooling fold
        for (int mt = 0; mt < 8; mt++) {
            float d[2][4];
#pragma unroll
            for (int nt = 0; nt < 2; nt++)
#pragma unroll
                for (int e = 0; e < 4; e++) d[nt][e] = 0.f;
#pragma unroll
            for (int kc = 0; kc < 8; kc++) {
                const int off = (mt * 8 + kc) * 128 + lane * 4;
                const uint4 ah = *(const uint4*)&s_Ah[off];
                const uint4 al = *(const uint4*)&s_Al[off];
#pragma unroll
                for (int nt = 0; nt < 2; nt++) {
                    hmma_tf32(d[nt], ah, Bh[kc][nt][0], Bh[kc][nt][1]);
                    hmma_tf32(d[nt], ah, Bl[kc][nt][0], Bl[kc][nt][1]);
                    hmma_tf32(d[nt], al, Bh[kc][nt][0], Bh[kc][nt][1]);
                }
            }
#pragma unroll
            for (int nt = 0; nt < 2; nt++) {
                const float y0 = fmaxf(d[nt][0] + bcol[nt][0], 0.f);
                const float y1 = fmaxf(d[nt][1] + bcol[nt][1], 0.f);
                const float y2 = fmaxf(d[nt][2] + bcol[nt][0], 0.f);
                const float y3 = fmaxf(d[nt][3] + bcol[nt][1], 0.f);
                psum[nt][0] += y0; pmax[nt][0] = fmaxf(pmax[nt][0], y0);
                psum[nt][1] += y1; pmax[nt][1] = fmaxf(pmax[nt][1], y1);
                psum[nt][2] += y2; pmax[nt][2] = fmaxf(pmax[nt][2], y2);
                psum[nt][3] += y3; pmax[nt][3] = fmaxf(pmax[nt][3], y3);
            }
        }
    }

    // reduce rows (lane bits 2..4) per column, write chunk partials
#pragma unroll
    for (int nt = 0; nt < 2; nt++) {
        float sc0 = psum[nt][0] + psum[nt][2];
        float sc1 = psum[nt][1] + psum[nt][3];
        float mc0 = fmaxf(pmax[nt][0], pmax[nt][2]);
        float mc1 = fmaxf(pmax[nt][1], pmax[nt][3]);
#pragma unroll
        for (int ofs = 4; ofs <= 16; ofs <<= 1) {
            sc0 += __shfl_xor_sync(0xffffffffu, sc0, ofs);
            sc1 += __shfl_xor_sync(0xffffffffu, sc1, ofs);
            mc0 = fmaxf(mc0, __shfl_xor_sync(0xffffffffu, mc0, ofs));
            mc1 = fmaxf(mc1, __shfl_xor_sync(0xffffffffu, mc1, ofs));
        }
        if (lane < 4) {
            const int d0 = 16 * wid + nt * 8 + 2 * lane;
            g_psum[b][chunk][d0]     = sc0;
            g_psum[b][chunk][d0 + 1] = sc1;
            g_pmax[b][chunk][d0]     = mc0;
            g_pmax[b][chunk][d0 + 1] = mc1;
        }
    }
}

// ---------------------------------------------------------------------------
// K1b: fp32 tail (nodes 9984..9999) + combine partials -> pooled + pproj.
// ---------------------------------------------------------------------------
__global__ __launch_bounds__(256) void k_pool(
    const float* __restrict__ x,
    const float* __restrict__ fw1, const float* __restrict__ fb1,
    const float* __restrict__ fw2, const float* __restrict__ fb2,
    const float* __restrict__ aw1)
{
    __shared__ float s_h[NTAIL * H];
    __shared__ float s_ts[2][ND];
    __shared__ float s_tm[2][ND];
    __shared__ float s_pool[2 * ND];

    const int b = blockIdx.x, tid = threadIdx.x;

#pragma unroll
    for (int i = 0; i < 4; i++) {
        const int v = tid + i * 256;
        const int n = v >> 6, k = v & 63;
        const float* xp = x + ((long)b * NN + (NN - NTAIL) + n) * 3;
        const float h = fmaf(xp[0], fw1[k],
                        fmaf(xp[1], fw1[H + k],
                        fmaf(xp[2], fw1[2 * H + k], fb1[k])));
        s_h[n * H + k] = fmaxf(h, 0.f);
    }
    __syncthreads();

    {
        const int d = tid & 127, half = tid >> 7;
        float ts = 0.f, tm = 0.f;
        for (int n = half * 8; n < half * 8 + 8; n++) {
            float a = fb2[d];
            for (int k = 0; k < H; k++)
                a = fmaf(s_h[n * H + k], __ldg(fw2 + k * ND + d), a);
            const float y = fmaxf(a, 0.f);
            ts += y;
            tm = fmaxf(tm, y);
        }
        s_ts[half][d] = ts;
        s_tm[half][d] = tm;
    }
    __syncthreads();

    if (tid < ND) {
        float s = s_ts[0][tid] + s_ts[1][tid];
        float m = fmaxf(s_tm[0][tid], s_tm[1][tid]);
#pragma unroll
        for (int ch = 0; ch < NCH; ch++) {
            s += g_psum[b][ch][tid];
            m = fmaxf(m, g_pmax[b][ch][tid]);
        }
        const float mean = s * (1.f / NN);
        g_pooled[b][tid] = mean;
        g_pooled[b][ND + tid] = m;
        s_pool[tid] = mean;
        s_pool[ND + tid] = m;
    }
    __syncthreads();

    float pc = 0.f;
    for (int i = 0; i < 2 * ND; i++)
        pc = fmaf(s_pool[i], __ldg(aw1 + (ND + i) * HA + tid), pc);
    g_pproj[b][tid] = pc;
}

// ---------------------------------------------------------------------------
// K2: actor — exact R5 version (proven 114us). Thread owns j and j+128.
// ---------------------------------------------------------------------------
__global__ __launch_bounds__(128) void k_actor(
    const float* __restrict__ x, const int* __restrict__ cand,
    const float* __restrict__ fw1, const float* __restrict__ fb1,
    const float* __restrict__ fw2, const float* __restrict__ fb2,
    const float* __restrict__ aw1, const float* __restrict__ ab1,
    const float* __restrict__ aw2, const float* __restrict__ ab2,
    const float* __restrict__ aw3, const float* __restrict__ ab3)
{
    extern __shared__ float sm[];
    float* s_feat = sm;                      // ND*FS
    float* s_mid  = s_feat + ND * FS;        // HA*MS
    float* s_hT   = s_mid + HA * MS;         // H*CC
    float* s_x    = s_hT + H * CC;           // CC*3
    float* s_w1t  = s_x + CC * 3;            // H*4
    float* s_red  = s_w1t + H * 4;           // 4*CC

    const int tid = threadIdx.x;
    const int b = blockIdx.y;
    const int c0 = blockIdx.x * CC;
    const int nvalid = min(CC, NC - c0);

    if (tid < H) {
        s_w1t[tid * 4 + 0] = fw1[tid];
        s_w1t[tid * 4 + 1] = fw1[H + tid];
        s_w1t[tid * 4 + 2] = fw1[2 * H + tid];
        s_w1t[tid * 4 + 3] = fb1[tid];
    }
    if (tid < CC * 3) {
        const int c = tid / 3, i = tid - c * 3;
        float v = 0.f;
        if (c < nvalid) {
            const int node = cand[b * NC + c0 + c];
            v = x[((long)b * NN + node) * 3 + i];
        }
        s_x[tid] = v;
    }
    __syncthreads();

    // fe layer 1 -> s_hT[k][c]
    {
        const int n1 = tid & 31, kg = tid >> 5;
        const float x0 = s_x[n1 * 3 + 0];
        const float x1 = s_x[n1 * 3 + 1];
        const float x2 = s_x[n1 * 3 + 2];
#pragma unroll
        for (int m = 0; m < 16; m++) {
            const int k = kg * 16 + m;
            const float4 w = *(const float4*)&s_w1t[k * 4];
            const float v = fmaf(x0, w.x, fmaf(x1, w.y, fmaf(x2, w.z, w.w)));
            s_hT[k * CC + n1] = fmaxf(v, 0.f);
        }
    }
    __syncthreads();

    // fe layer 2 -> s_feat[d][c]
    {
        const int dg = tid >> 1, ph = tid & 1;
        const int d0 = 2 * dg, d1 = d0 + 1;
        unsigned long long a2[16];
#pragma unroll
        for (int p = 0; p < 16; p++) a2[p] = 0ull;
#pragma unroll 4
        for (int k = 0; k < H; k++) {
            const float2 wp = __ldg((const float2*)(fw2 + k * ND + d0));
            const unsigned long long w0 = dup2(wp.x);
            const unsigned long long w1d = dup2(wp.y);
            const ulonglong2* row = (const ulonglong2*)(s_hT + k * CC + ph * 16);
#pragma unroll
            for (int q = 0; q < 4; q++) {
                const ulonglong2 h2 = row[q];
                a2[4 * q + 0] = fma2(h2.x, w0,  a2[4 * q + 0]);
                a2[4 * q + 1] = fma2(h2.x, w1d, a2[4 * q + 1]);
                a2[4 * q + 2] = fma2(h2.y, w0,  a2[4 * q + 2]);
                a2[4 * q + 3] = fma2(h2.y, w1d, a2[4 * q + 3]);
            }
        }
        const float b20 = fb2[d0], b21 = fb2[d1];
#pragma unroll
        for (int q = 0; q < 4; q++) {
            const int cb = ph * 16 + 4 * q;
            float lo, hi;
            unpack2(a2[4 * q + 0], lo, hi);
            s_feat[d0 * FS + cb]     = fmaxf(lo + b20, 0.f);
            s_feat[d0 * FS + cb + 1] = fmaxf(hi + b20, 0.f);
            unpack2(a2[4 * q + 1], lo, hi);
            s_feat[d1 * FS + cb]     = fmaxf(lo + b21, 0.f);
            s_feat[d1 * FS + cb + 1] = fmaxf(hi + b21, 0.f);
            unpack2(a2[4 * q + 2], lo, hi);
            s_feat[d0 * FS + cb + 2] = fmaxf(lo + b20, 0.f);
            s_feat[d0 * FS + cb + 3] = fmaxf(hi + b20, 0.f);
            unpack2(a2[4 * q + 3], lo, hi);
            s_feat[d1 * FS + cb + 2] = fmaxf(lo + b21, 0.f);
            s_feat[d1 * FS + cb + 3] = fmaxf(hi + b21, 0.f);
        }
    }
    __syncthreads();

    const int j0 = tid, j1 = tid + 128;
    unsigned long long acc[32];

#pragma unroll
    for (int p = 0; p < 32; p++) acc[p] = 0ull;
#pragma unroll 2
    for (int i = 0; i < ND; i++) {
        const unsigned long long w0 = dup2(__ldg(aw1 + i * HA + j0));
        const unsigned long long w1d = dup2(__ldg(aw1 + i * HA + j1));
        const ulonglong2* row = (const ulonglong2*)(s_feat + i * FS);
#pragma unroll
        for (int q = 0; q < 8; q++) {
            const ulonglong2 f2 = row[q];
            acc[4 * q + 0] = fma2(f2.x, w0,  acc[4 * q + 0]);
            acc[4 * q + 1] = fma2(f2.x, w1d, acc[4 * q + 1]);
            acc[4 * q + 2] = fma2(f2.y, w0,  acc[4 * q + 2]);
            acc[4 * q + 3] = fma2(f2.y, w1d, acc[4 * q + 3]);
        }
    }
    {
        const float bj0 = ab1[j0] + g_pproj[b][j0];
        const float bj1 = ab1[j1] + g_pproj[b][j1];
#pragma unroll
        for (int q = 0; q < 8; q++) {
            float lo, hi;
            const int cb = 4 * q;
            unpack2(acc[4 * q + 0], lo, hi);
            s_mid[j0 * MS + cb]     = tanhf(lo + bj0);
            s_mid[j0 * MS + cb + 1] = tanhf(hi + bj0);
            unpack2(acc[4 * q + 1], lo, hi);
            s_mid[j1 * MS + cb]     = tanhf(lo + bj1);
            s_mid[j1 * MS + cb + 1] = tanhf(hi + bj1);
            unpack2(acc[4 * q + 2], lo, hi);
            s_mid[j0 * MS + cb + 2] = tanhf(lo + bj0);
            s_mid[j0 * MS + cb + 3] = tanhf(hi + bj0);
            unpack2(acc[4 * q + 3], lo, hi);
            s_mid[j1 * MS + cb + 2] = tanhf(lo + bj1);
            s_mid[j1 * MS + cb + 3] = tanhf(hi + bj1);
        }
    }
    __syncthreads();

#pragma unroll
    for (int p = 0; p < 32; p++) acc[p] = 0ull;
#pragma unroll 2
    for (int i = 0; i < HA; i++) {
        const unsigned long long w0 = dup2(__ldg(aw2 + i * HA + j0));
        const unsigned long long w1d = dup2(__ldg(aw2 + i * HA + j1));
        const ulonglong2* row = (const ulonglong2*)(s_mid + i * MS);
#pragma unroll
        for (int q = 0; q < 8; q++) {
            const ulonglong2 f2 = row[q];
            acc[4 * q + 0] = fma2(f2.x, w0,  acc[4 * q + 0]);
            acc[4 * q + 1] = fma2(f2.x, w1d, acc[4 * q + 1]);
            acc[4 * q + 2] = fma2(f2.y, w0,  acc[4 * q + 2]);
            acc[4 * q + 3] = fma2(f2.y, w1d, acc[4 * q + 3]);
        }
    }

    {
        const float bj0 = ab2[j0], bj1 = ab2[j1];
        const float w30 = aw3[j0], w31 = aw3[j1];
        float vc[CC];
#pragma unroll
        for (int q = 0; q < 8; q++) {
            const int cb = 4 * q;
            float t0lo, t0hi, t2lo, t2hi;
            unpack2(acc[4 * q + 0], t0lo, t0hi);
            unpack2(acc[4 * q + 2], t2lo, t2hi);
            float u0lo, u0hi, u2lo, u2hi;
            unpack2(acc[4 * q + 1], u0lo, u0hi);
            unpack2(acc[4 * q + 3], u2lo, u2hi);
            vc[cb]     = tanhf(t0lo + bj0) * w30 + tanhf(u0lo + bj1) * w31;
            vc[cb + 1] = tanhf(t0hi + bj0) * w30 + tanhf(u0hi + bj1) * w31;
            vc[cb + 2] = tanhf(t2lo + bj0) * w30 + tanhf(u2lo + bj1) * w31;
            vc[cb + 3] = tanhf(t2hi + bj0) * w30 + tanhf(u2hi + bj1) * w31;
        }
        const int lane = tid & 31, warp = tid >> 5;
#pragma unroll
        for (int c = 0; c < CC; c++) {
            float v = vc[c];
            v += __shfl_xor_sync(0xffffffffu, v, 16);
            v += __shfl_xor_sync(0xffffffffu, v, 8);
            v += __shfl_xor_sync(0xffffffffu, v, 4);
            v += __shfl_xor_sync(0xffffffffu, v, 2);
            v += __shfl_xor_sync(0xffffffffu, v, 1);
            if (lane == 0) s_red[warp * CC + c] = v;
        }
    }
    __syncthreads();
    if (tid < CC) {
        float s = ab3[0];
#pragma unroll
        for (int w = 0; w < 4; w++) s += s_red[w * CC + tid];
        if (tid < nvalid) g_scores[b][c0 + tid] = s;
    }
}

// ---------------------------------------------------------------------------
// K3: critic MLP on pooled feature + masked softmax over candidates.
// ---------------------------------------------------------------------------
__global__ __launch_bounds__(256) void k_final(
    const unsigned char* __restrict__ mask,
    const float* __restrict__ cw1, const float* __restrict__ cb1,
    const float* __restrict__ cw2, const float* __restrict__ cb2,
    const float* __restrict__ cw3, const float* __restrict__ cb3,
    float* __restrict__ out)
{
    __shared__ float s_in[HA];
    __shared__ float s_hid[HA];
    __shared__ float s_r[8];
    __shared__ float s_b0, s_b1v;

    const int tid = threadIdx.x, b = blockIdx.x;
    const int lane = tid & 31, warp = tid >> 5;

    s_in[tid] = g_pooled[b][tid];
    __syncthreads();
    float acc = cb1[tid];
    for (int i = 0; i < HA; i++) acc = fmaf(s_in[i], cw1[i * HA + tid], acc);
    s_hid[tid] = tanhf(acc);
    __syncthreads();
    acc = cb2[tid];
    for (int i = 0; i < HA; i++) acc = fmaf(s_hid[i], cw2[i * HA + tid], acc);
    {
        float p = tanhf(acc) * cw3[tid];
        p += __shfl_xor_sync(0xffffffffu, p, 16);
        p += __shfl_xor_sync(0xffffffffu, p, 8);
        p += __shfl_xor_sync(0xffffffffu, p, 4);
        p += __shfl_xor_sync(0xffffffffu, p, 2);
        p += __shfl_xor_sync(0xffffffffu, p, 1);
        if (lane == 0) s_r[warp] = p;
    }
    __syncthreads();
    if (tid == 0) {
        float v = cb3[0];
#pragma unroll
        for (int w = 0; w < 8; w++) v += s_r[w];
        out[BATCH * NC + b] = v;
    }

    const int c = tid;
    bool valid = false;
    float s = -FLT_MAX;
    if (c < NC) {
        const int mi = b * NC + c;
        const int mv = g_mask_i32 ? ((const int*)mask)[mi] : (int)mask[mi];
        valid = (mv != 0);
        if (valid) s = g_scores[b][c];
    }
    float m = s;
    m = fmaxf(m, __shfl_xor_sync(0xffffffffu, m, 16));
    m = fmaxf(m, __shfl_xor_sync(0xffffffffu, m, 8));
    m = fmaxf(m, __shfl_xor_sync(0xffffffffu, m, 4));
    m = fmaxf(m, __shfl_xor_sync(0xffffffffu, m, 2));
    m = fmaxf(m, __shfl_xor_sync(0xffffffffu, m, 1));
    __syncthreads();
    if (lane == 0) s_r[warp] = m;
    __syncthreads();
    if (warp == 0) {
        float t = (lane < 8) ? s_r[lane] : -FLT_MAX;
        t = fmaxf(t, __shfl_xor_sync(0xffffffffu, t, 4));
        t = fmaxf(t, __shfl_xor_sync(0xffffffffu, t, 2));
        t = fmaxf(t, __shfl_xor_sync(0xffffffffu, t, 1));
        if (lane == 0) s_b0 = t;
    }
    __syncthreads();
    const float mx = s_b0;
    const float e = valid ? expf(s - mx) : 0.f;
    float se = e;
    se += __shfl_xor_sync(0xffffffffu, se, 16);
    se += __shfl_xor_sync(0xffffffffu, se, 8);
    se += __shfl_xor_sync(0xffffffffu, se, 4);
    se += __shfl_xor_sync(0xffffffffu, se, 2);
    se += __shfl_xor_sync(0xffffffffu, se, 1);
    __syncthreads();
    if (lane == 0) s_r[warp] = se;
    __syncthreads();
    if (warp == 0) {
        float t = (lane < 8) ? s_r[lane] : 0.f;
        t += __shfl_xor_sync(0xffffffffu, t, 4);
        t += __shfl_xor_sync(0xffffffffu, t, 2);
        t += __shfl_xor_sync(0xffffffffu, t, 1);
        if (lane == 0) s_b1v = t;
    }
    __syncthreads();
    if (c < NC) out[b * NC + c] = e / s_b1v;
}

// ---------------------------------------------------------------------------
extern "C" void kernel_launch(void* const* d_in, const int* in_sizes, int n_in,
                              void* d_out, int out_size)
{
    const float* x    = (const float*)d_in[0];
    const int*   cand = (const int*)d_in[1];
    const unsigned char* mask = (const unsigned char*)d_in[2];
    const float* fw1 = (const float*)d_in[3];
    const float* fb1 = (const float*)d_in[4];
    const float* fw2 = (const float*)d_in[5];
    const float* fb2 = (const float*)d_in[6];
    const float* aw1 = (const float*)d_in[7];
    const float* ab1 = (const float*)d_in[8];
    const float* aw2 = (const float*)d_in[9];
    const float* ab2 = (const float*)d_in[10];
    const float* aw3 = (const float*)d_in[11];
    const float* ab3 = (const float*)d_in[12];
    const float* cw1 = (const float*)d_in[13];
    const float* cb1 = (const float*)d_in[14];
    const float* cw2 = (const float*)d_in[15];
    const float* cb2 = (const float*)d_in[16];
    const float* cw3 = (const float*)d_in[17];
    const float* cb3 = (const float*)d_in[18];
    float* out = (float*)d_out;

    const int smem_actor =
        (ND * FS + HA * MS + H * CC + CC * 3 + H * 4 + 4 * CC) * (int)sizeof(float);
    cudaFuncSetAttribute(k_actor, cudaFuncAttributeMaxDynamicSharedMemorySize,
                         smem_actor);
    const int smem_fp = 2 * 8192 * (int)sizeof(uint32_t);   // A_hi + A_lo = 64KB
    cudaFuncSetAttribute(k_featpool_wmma,
                         cudaFuncAttributeMaxDynamicSharedMemorySize, smem_fp);

    k_sniff<<<1, 32>>>(mask);
    k_featpool_wmma<<<dim3(NCH, BATCH), 256, smem_fp>>>(x, fw1, fb1, fw2, fb2);
    k_pool<<<BATCH, 256>>>(x, fw1, fb1, fw2, fb2, aw1);
    k_actor<<<dim3(NCHUNK, BATCH), 128, smem_actor>>>(
        x, cand, fw1, fb1, fw2, fb2, aw1, ab1, aw2, ab2, aw3, ab3);
    k_final<<<BATCH, 256>>>(mask, cw1, cb1, cw2, cb2, cw3, cb3, out);
}

// round 10
// speedup vs baseline: 1.3864x; 1.0812x over previous
#include <cuda_runtime.h>
#include <math.h>
#include <float.h>
#include <stdint.h>

// Problem dims
#define BATCH 64
#define NN    10000
#define NC    201
#define H     64
#define ND    128      // node feature dim (2H)
#define HA    256      // actor/critic hidden
#define NCH   6        // chunks per batch (wmma featpool)
#define TPT   13       // 128-node tiles per chunk (6*13*128 = 9984)
#define NTAIL 16       // tail nodes handled in k_pool
#define CC    32       // candidates per actor block
#define NCHUNK 7       // ceil(201/32)

// Scratch (device globals: no allocation allowed)
__device__ float g_psum[BATCH][NCH][ND];
__device__ float g_pmax[BATCH][NCH][ND];
__device__ float g_pooled[BATCH][2 * ND];
__device__ float g_pproj[BATCH][HA];
__device__ float g_scores[BATCH][NC];
__device__ int   g_mask_i32;
// Pre-split fragment-packed actor weights: (bh0, bh1, bl0, bl1) per lane.
__device__ uint4 g_awf1[16 * 32 * 32];   // [kc 16][ntg 32][lane 32]
__device__ uint4 g_awf2[32 * 32 * 32];   // [kc 32][ntg 32][lane 32]

// ---- f32x2 packed helpers ----
static __device__ __forceinline__ unsigned long long dup2(float w) {
    unsigned long long r;
    unsigned int b = __float_as_uint(w);
    asm("mov.b64 %0, {%1, %1};" : "=l"(r) : "r"(b));
    return r;
}
static __device__ __forceinline__ unsigned long long fma2(
    unsigned long long a, unsigned long long b, unsigned long long c) {
    unsigned long long d;
    asm("fma.rn.f32x2 %0, %1, %2, %3;" : "=l"(d) : "l"(a), "l"(b), "l"(c));
    return d;
}
static __device__ __forceinline__ void unpack2(unsigned long long v, float& lo, float& hi) {
    unsigned int a, b;
    asm("mov.b64 {%0, %1}, %2;" : "=r"(a), "=r"(b) : "l"(v));
    lo = __uint_as_float(a);
    hi = __uint_as_float(b);
}

// ---- tf32 warp-MMA helpers (sm_80+ generic) ----
static __device__ __forceinline__ uint32_t to_tf32(float f) {
    uint32_t r;
    asm("cvt.rna.tf32.f32 %0, %1;" : "=r"(r) : "f"(f));
    return r;
}
static __device__ __forceinline__ void split_tf32(float f, uint32_t& hi, uint32_t& lo) {
    hi = to_tf32(f);
    lo = to_tf32(f - __uint_as_float(hi));
}
static __device__ __forceinline__ void hmma_tf32(
    float* d, const uint4& a, uint32_t b0, uint32_t b1) {
    asm volatile(
        "mma.sync.aligned.m16n8k8.row.col.f32.tf32.tf32.f32 "
        "{%0,%1,%2,%3}, {%4,%5,%6,%7}, {%8,%9}, {%0,%1,%2,%3};"
        : "+f"(d[0]), "+f"(d[1]), "+f"(d[2]), "+f"(d[3])
        : "r"(a.x), "r"(a.y), "r"(a.z), "r"(a.w), "r"(b0), "r"(b1));
}

// ---------------------------------------------------------------------------
// K0: sniff mask dtype.
// ---------------------------------------------------------------------------
__global__ void k_sniff(const unsigned char* __restrict__ m) {
    if (threadIdx.x == 0) {
        int any = 0;
        for (int i = 0; i < 1024; i++)
            if ((i & 3) && m[i]) any = 1;
        g_mask_i32 = any ? 0 : 1;
    }
}

// ---------------------------------------------------------------------------
// K0b: pre-split actor weights into fragment-packed hi/lo (shared by all blocks).
// ---------------------------------------------------------------------------
__global__ __launch_bounds__(256) void k_wsplit(
    const float* __restrict__ aw1, const float* __restrict__ aw2)
{
    const int t = blockIdx.x * 256 + threadIdx.x;
    const int n1 = 16 * 32 * 32;
    if (t < n1) {
        const int lane = t & 31, ntg = (t >> 5) & 31, kc = t >> 10;
        const int gid = lane >> 2, tig = lane & 3;
        const int j = ntg * 8 + gid;
        const float w0 = aw1[(kc * 8 + tig) * HA + j];
        const float w1v = aw1[(kc * 8 + tig + 4) * HA + j];
        uint4 v;
        split_tf32(w0, v.x, v.z);
        split_tf32(w1v, v.y, v.w);
        g_awf1[t] = v;
    } else {
        const int t2 = t - n1;
        const int lane = t2 & 31, ntg = (t2 >> 5) & 31, kc = t2 >> 10;
        const int gid = lane >> 2, tig = lane & 3;
        const int j = ntg * 8 + gid;
        const float w0 = aw2[(kc * 8 + tig) * HA + j];
        const float w1v = aw2[(kc * 8 + tig + 4) * HA + j];
        uint4 v;
        split_tf32(w0, v.x, v.z);
        split_tf32(w1v, v.y, v.w);
        g_awf2[t2] = v;
    }
}

// ---------------------------------------------------------------------------
// K1: featpool via 3xTF32 warp MMA (R9, proven).
// ---------------------------------------------------------------------------
__global__ __launch_bounds__(256) void k_featpool_wmma(
    const float* __restrict__ x,
    const float* __restrict__ w1, const float* __restrict__ b1,
    const float* __restrict__ w2, const float* __restrict__ b2)
{
    extern __shared__ __align__(16) uint32_t s_dyn[];
    uint32_t* s_Ah = s_dyn;
    uint32_t* s_Al = s_dyn + 8192;
    __shared__ __align__(16) float4 s_x4[128];
    __shared__ __align__(16) float s_w1t[H][4];

    const int tid = threadIdx.x;
    const int wid = tid >> 5, lane = tid & 31;
    const int b = blockIdx.y, chunk = blockIdx.x;
    const int base = chunk * TPT * 128;
    const int tig = lane & 3;
    const int gid = lane >> 2;

    if (tid < H) {
        s_w1t[tid][0] = w1[tid];
        s_w1t[tid][1] = w1[H + tid];
        s_w1t[tid][2] = w1[2 * H + tid];
        s_w1t[tid][3] = b1[tid];
    }

    uint32_t Bh[8][2][2], Bl[8][2][2];
#pragma unroll
    for (int kc = 0; kc < 8; kc++)
#pragma unroll
        for (int nt = 0; nt < 2; nt++) {
            const int k0 = kc * 8 + tig;
            const int d = 16 * wid + nt * 8 + gid;
            split_tf32(__ldg(w2 + k0 * ND + d),       Bh[kc][nt][0], Bl[kc][nt][0]);
            split_tf32(__ldg(w2 + (k0 + 4) * ND + d), Bh[kc][nt][1], Bl[kc][nt][1]);
        }

    float bcol[2][2];
#pragma unroll
    for (int nt = 0; nt < 2; nt++) {
        const int d0 = 16 * wid + nt * 8 + 2 * tig;
        bcol[nt][0] = b2[d0];
        bcol[nt][1] = b2[d0 + 1];
    }

    float psum[2][4], pmax[2][4];
#pragma unroll
    for (int nt = 0; nt < 2; nt++)
#pragma unroll
        for (int e = 0; e < 4; e++) { psum[nt][e] = 0.f; pmax[nt][e] = 0.f; }

    __syncthreads();

    for (int t = 0; t < TPT; t++) {
        if (tid < 128) {
            const int node = base + t * 128 + tid;
            const float* xp = x + ((long)b * NN + node) * 3;
            s_x4[tid] = make_float4(xp[0], xp[1], xp[2], 0.f);
        }
        __syncthreads();

#pragma unroll
        for (int q = 0; q < 8; q++) {
            const int slot = q * 256 + tid;
            const int mt = slot >> 8;
            const int kc = (slot >> 5) & 7;
            const int ln = slot & 31;
            const int r = ln >> 2, c = ln & 3;
            const float4 xa = s_x4[mt * 16 + r];
            const float4 xb = s_x4[mt * 16 + r + 8];
            const float4 wA = *(const float4*)&s_w1t[kc * 8 + c][0];
            const float4 wB = *(const float4*)&s_w1t[kc * 8 + c + 4][0];
            const float h00 = fmaxf(fmaf(xa.x, wA.x, fmaf(xa.y, wA.y, fmaf(xa.z, wA.z, wA.w))), 0.f);
            const float h10 = fmaxf(fmaf(xb.x, wA.x, fmaf(xb.y, wA.y, fmaf(xb.z, wA.z, wA.w))), 0.f);
            const float h01 = fmaxf(fmaf(xa.x, wB.x, fmaf(xa.y, wB.y, fmaf(xa.z, wB.z, wB.w))), 0.f);
            const float h11 = fmaxf(fmaf(xb.x, wB.x, fmaf(xb.y, wB.y, fmaf(xb.z, wB.z, wB.w))), 0.f);
            uint4 vh, vl;
            split_tf32(h00, vh.x, vl.x);
            split_tf32(h10, vh.y, vl.y);
            split_tf32(h01, vh.z, vl.z);
            split_tf32(h11, vh.w, vl.w);
            const int off = (mt * 8 + kc) * 128 + ln * 4;
            *(uint4*)&s_Ah[off] = vh;
            *(uint4*)&s_Al[off] = vl;
        }
        __syncthreads();

        for (int mt = 0; mt < 8; mt++) {
            float d[2][4];
#pragma unroll
            for (int nt = 0; nt < 2; nt++)
#pragma unroll
                for (int e = 0; e < 4; e++) d[nt][e] = 0.f;
#pragma unroll
            for (int kc = 0; kc < 8; kc++) {
                const int off = (mt * 8 + kc) * 128 + lane * 4;
                const uint4 ah = *(const uint4*)&s_Ah[off];
                const uint4 al = *(const uint4*)&s_Al[off];
#pragma unroll
                for (int nt = 0; nt < 2; nt++) {
                    hmma_tf32(d[nt], ah, Bh[kc][nt][0], Bh[kc][nt][1]);
                    hmma_tf32(d[nt], ah, Bl[kc][nt][0], Bl[kc][nt][1]);
                    hmma_tf32(d[nt], al, Bh[kc][nt][0], Bh[kc][nt][1]);
                }
            }
#pragma unroll
            for (int nt = 0; nt < 2; nt++) {
                const float y0 = fmaxf(d[nt][0] + bcol[nt][0], 0.f);
                const float y1 = fmaxf(d[nt][1] + bcol[nt][1], 0.f);
                const float y2 = fmaxf(d[nt][2] + bcol[nt][0], 0.f);
                const float y3 = fmaxf(d[nt][3] + bcol[nt][1], 0.f);
                psum[nt][0] += y0; pmax[nt][0] = fmaxf(pmax[nt][0], y0);
                psum[nt][1] += y1; pmax[nt][1] = fmaxf(pmax[nt][1], y1);
                psum[nt][2] += y2; pmax[nt][2] = fmaxf(pmax[nt][2], y2);
                psum[nt][3] += y3; pmax[nt][3] = fmaxf(pmax[nt][3], y3);
            }
        }
    }

#pragma unroll
    for (int nt = 0; nt < 2; nt++) {
        float sc0 = psum[nt][0] + psum[nt][2];
        float sc1 = psum[nt][1] + psum[nt][3];
        float mc0 = fmaxf(pmax[nt][0], pmax[nt][2]);
        float mc1 = fmaxf(pmax[nt][1], pmax[nt][3]);
#pragma unroll
        for (int ofs = 4; ofs <= 16; ofs <<= 1) {
            sc0 += __shfl_xor_sync(0xffffffffu, sc0, ofs);
            sc1 += __shfl_xor_sync(0xffffffffu, sc1, ofs);
            mc0 = fmaxf(mc0, __shfl_xor_sync(0xffffffffu, mc0, ofs));
            mc1 = fmaxf(mc1, __shfl_xor_sync(0xffffffffu, mc1, ofs));
        }
        if (lane < 4) {
            const int d0 = 16 * wid + nt * 8 + 2 * lane;
            g_psum[b][chunk][d0]     = sc0;
            g_psum[b][chunk][d0 + 1] = sc1;
            g_pmax[b][chunk][d0]     = mc0;
            g_pmax[b][chunk][d0 + 1] = mc1;
        }
    }
}

// ---------------------------------------------------------------------------
// K1b: fp32 tail + combine partials -> pooled + pproj (R9, proven).
// ---------------------------------------------------------------------------
__global__ __launch_bounds__(256) void k_pool(
    const float* __restrict__ x,
    const float* __restrict__ fw1, const float* __restrict__ fb1,
    const float* __restrict__ fw2, const float* __restrict__ fb2,
    const float* __restrict__ aw1)
{
    __shared__ float s_h[NTAIL * H];
    __shared__ float s_ts[2][ND];
    __shared__ float s_tm[2][ND];
    __shared__ float s_pool[2 * ND];

    const int b = blockIdx.x, tid = threadIdx.x;

#pragma unroll
    for (int i = 0; i < 4; i++) {
        const int v = tid + i * 256;
        const int n = v >> 6, k = v & 63;
        const float* xp = x + ((long)b * NN + (NN - NTAIL) + n) * 3;
        const float h = fmaf(xp[0], fw1[k],
                        fmaf(xp[1], fw1[H + k],
                        fmaf(xp[2], fw1[2 * H + k], fb1[k])));
        s_h[n * H + k] = fmaxf(h, 0.f);
    }
    __syncthreads();

    {
        const int d = tid & 127, half = tid >> 7;
        float ts = 0.f, tm = 0.f;
        for (int n = half * 8; n < half * 8 + 8; n++) {
            float a = fb2[d];
            for (int k = 0; k < H; k++)
                a = fmaf(s_h[n * H + k], __ldg(fw2 + k * ND + d), a);
            const float y = fmaxf(a, 0.f);
            ts += y;
            tm = fmaxf(tm, y);
        }
        s_ts[half][d] = ts;
        s_tm[half][d] = tm;
    }
    __syncthreads();

    if (tid < ND) {
        float s = s_ts[0][tid] + s_ts[1][tid];
        float m = fmaxf(s_tm[0][tid], s_tm[1][tid]);
#pragma unroll
        for (int ch = 0; ch < NCH; ch++) {
            s += g_psum[b][ch][tid];
            m = fmaxf(m, g_pmax[b][ch][tid]);
        }
        const float mean = s * (1.f / NN);
        g_pooled[b][tid] = mean;
        g_pooled[b][ND + tid] = m;
        s_pool[tid] = mean;
        s_pool[ND + tid] = m;
    }
    __syncthreads();

    float pc = 0.f;
    for (int i = 0; i < 2 * ND; i++)
        pc = fmaf(s_pool[i], __ldg(aw1 + (ND + i) * HA + tid), pc);
    g_pproj[b][tid] = pc;
}

// ---------------------------------------------------------------------------
// K2: actor via 3xTF32 warp MMA.
// Block = 256 thr (8 warps). Warp w owns output n-tiles ntg = 4w..4w+3 (8 j's
// each). m = 32 candidates = 2 m-tiles. Layer-1 k = 128 feat (16 kc), layer-2
// k = 256 mid (32 kc). A fragments staged in smem hi/lo; B fragments from
// pre-split packed globals (1 LDG.128 each). tanh epilogues scatter into the
// next layer's A-fragment slots.
// Dynamic smem (u32): fA 4096 | fAl 4096 | mA 8192 | mAl 8192 | hT 2048 |
//                     x 96 | w1t 256 | red 256  => 27232 u32 = 108928 B.
// ---------------------------------------------------------------------------
__global__ __launch_bounds__(256, 2) void k_actor_mma(
    const float* __restrict__ x, const int* __restrict__ cand,
    const float* __restrict__ fw1, const float* __restrict__ fb1,
    const float* __restrict__ fw2, const float* __restrict__ fb2,
    const float* __restrict__ ab1, const float* __restrict__ ab2,
    const float* __restrict__ aw3, const float* __restrict__ ab3)
{
    extern __shared__ __align__(16) uint32_t sA[];
    uint32_t* s_fA  = sA;              // 4096
    uint32_t* s_fAl = sA + 4096;       // 4096
    uint32_t* s_mA  = sA + 8192;       // 8192
    uint32_t* s_mAl = sA + 16384;      // 8192
    float* s_hT  = (float*)(sA + 24576);   // 2048 (64 k x 32 c)
    float* s_x   = s_hT + 2048;            // 96
    float* s_w1t = s_x + 96;               // 256
    float* s_red = s_w1t + 256;            // 256 (8 warps x 32 c)

    const int tid = threadIdx.x;
    const int w = tid >> 5, lane = tid & 31;
    const int gid = lane >> 2, tig = lane & 3;
    const int b = blockIdx.y;
    const int c0 = blockIdx.x * CC;
    const int nvalid = min(CC, NC - c0);

    if (tid < H) {
        s_w1t[tid * 4 + 0] = fw1[tid];
        s_w1t[tid * 4 + 1] = fw1[H + tid];
        s_w1t[tid * 4 + 2] = fw1[2 * H + tid];
        s_w1t[tid * 4 + 3] = fb1[tid];
    }
    if (tid < CC * 3) {
        const int c = tid / 3, i = tid - c * 3;
        float v = 0.f;
        if (c < nvalid) {
            const int node = cand[b * NC + c0 + c];
            v = x[((long)b * NN + node) * 3 + i];
        }
        s_x[tid] = v;
    }
    __syncthreads();

    // fe layer 1 -> s_hT[k][c]  (256 thr: n1 = tid&31, kg = tid>>5 covers k in 8s)
    {
        const int n1 = tid & 31, kg = tid >> 5;
        const float x0 = s_x[n1 * 3 + 0];
        const float x1 = s_x[n1 * 3 + 1];
        const float x2 = s_x[n1 * 3 + 2];
#pragma unroll
        for (int m = 0; m < 8; m++) {
            const int k = kg * 8 + m;
            const float4 wv = *(const float4*)&s_w1t[k * 4];
            const float v = fmaf(x0, wv.x, fmaf(x1, wv.y, fmaf(x2, wv.z, wv.w)));
            s_hT[k * CC + n1] = fmaxf(v, 0.f);
        }
    }
    __syncthreads();

    // fe layer 2 -> feat fragments (hi/lo). Thread = (d = tid&127, half = tid>>7)
    // computes feat(c, d) for c = half*16 .. +16, scatters to A-frag slots.
    {
        const int d = tid & 127, half = tid >> 7;
        unsigned long long a2[8];
#pragma unroll
        for (int p = 0; p < 8; p++) a2[p] = 0ull;
#pragma unroll 4
        for (int k = 0; k < H; k++) {
            const unsigned long long wd = dup2(__ldg(fw2 + k * ND + d));
            const ulonglong2* row = (const ulonglong2*)(s_hT + k * CC + half * 16);
#pragma unroll
            for (int q = 0; q < 4; q++) {
                const ulonglong2 h2 = row[q];
                a2[2 * q]     = fma2(h2.x, wd, a2[2 * q]);
                a2[2 * q + 1] = fma2(h2.y, wd, a2[2 * q + 1]);
            }
        }
        const float b2d = fb2[d];
        const int kc = d >> 3, cc = d & 7;
        const int tileBase = (half * 16 + kc) * 128;
        const int laneCol = cc & 3, regCol = 2 * (cc >> 2);
#pragma unroll
        for (int p = 0; p < 8; p++) {
            float lo, hi;
            unpack2(a2[p], lo, hi);
            const float y0 = fmaxf(lo + b2d, 0.f);   // c_local = 2p
            const float y1 = fmaxf(hi + b2d, 0.f);   // c_local = 2p+1
            {
                const int rr = 2 * p;
                const int addr = tileBase + ((rr & 7) * 4 + laneCol) * 4 + (rr >> 3) + regCol;
                uint32_t vh, vl;
                split_tf32(y0, vh, vl);
                s_fA[addr] = vh; s_fAl[addr] = vl;
            }
            {
                const int rr = 2 * p + 1;
                const int addr = tileBase + ((rr & 7) * 4 + laneCol) * 4 + (rr >> 3) + regCol;
                uint32_t vh, vl;
                split_tf32(y1, vh, vl);
                s_fA[addr] = vh; s_fAl[addr] = vl;
            }
        }
    }

    // preload per-warp biases (j = (4w+nt)*8 + 2tig + {0,1})
    float bj1[4][2], bj2v[4][2], w3j[4][2];
#pragma unroll
    for (int nt = 0; nt < 4; nt++) {
        const int j0 = (4 * w + nt) * 8 + 2 * tig;
        bj1[nt][0] = ab1[j0] + g_pproj[b][j0];
        bj1[nt][1] = ab1[j0 + 1] + g_pproj[b][j0 + 1];
        bj2v[nt][0] = ab2[j0];     bj2v[nt][1] = ab2[j0 + 1];
        w3j[nt][0] = aw3[j0];      w3j[nt][1] = aw3[j0 + 1];
    }
    __syncthreads();

    float acc[2][4][4];

    // ---- layer 1 MMA: D1[c][j] over kc = 0..15 ----
#pragma unroll
    for (int mt = 0; mt < 2; mt++)
#pragma unroll
        for (int nt = 0; nt < 4; nt++)
#pragma unroll
            for (int e = 0; e < 4; e++) acc[mt][nt][e] = 0.f;

#pragma unroll 2
    for (int kc = 0; kc < 16; kc++) {
        const uint4 ah0 = *(const uint4*)&s_fA[kc * 128 + lane * 4];
        const uint4 al0 = *(const uint4*)&s_fAl[kc * 128 + lane * 4];
        const uint4 ah1 = *(const uint4*)&s_fA[(16 + kc) * 128 + lane * 4];
        const uint4 al1 = *(const uint4*)&s_fAl[(16 + kc) * 128 + lane * 4];
#pragma unroll
        for (int nt = 0; nt < 4; nt++) {
            const uint4 bf = __ldg(&g_awf1[(kc * 32 + 4 * w + nt) * 32 + lane]);
            hmma_tf32(acc[0][nt], ah0, bf.x, bf.y);
            hmma_tf32(acc[0][nt], ah0, bf.z, bf.w);
            hmma_tf32(acc[0][nt], al0, bf.x, bf.y);
            hmma_tf32(acc[1][nt], ah1, bf.x, bf.y);
            hmma_tf32(acc[1][nt], ah1, bf.z, bf.w);
            hmma_tf32(acc[1][nt], al1, bf.x, bf.y);
        }
    }

    // layer-1 epilogue: tanh -> mid fragments (layer-2 A layout)
#pragma unroll
    for (int mt = 0; mt < 2; mt++)
#pragma unroll
        for (int nt = 0; nt < 4; nt++) {
            const int ntg = 4 * w + nt;
            const int tileBase = (mt * 32 + ntg) * 128;
            const float v0 = tanhf(acc[mt][nt][0] + bj1[nt][0]);  // (gid,   2tig)
            const float v1 = tanhf(acc[mt][nt][1] + bj1[nt][1]);  // (gid,   2tig+1)
            const float v2 = tanhf(acc[mt][nt][2] + bj1[nt][0]);  // (gid+8, 2tig)
            const float v3 = tanhf(acc[mt][nt][3] + bj1[nt][1]);  // (gid+8, 2tig+1)
            const int cc0 = 2 * tig, cc1 = 2 * tig + 1;
            const int rc0 = 2 * (cc0 >> 2), rc1 = 2 * (cc1 >> 2);
            uint32_t vh, vl;
            int addr;
            addr = tileBase + (gid * 4 + (cc0 & 3)) * 4 + 0 + rc0;   // rr=gid
            split_tf32(v0, vh, vl); s_mA[addr] = vh; s_mAl[addr] = vl;
            addr = tileBase + (gid * 4 + (cc1 & 3)) * 4 + 0 + rc1;
            split_tf32(v1, vh, vl); s_mA[addr] = vh; s_mAl[addr] = vl;
            addr = tileBase + (gid * 4 + (cc0 & 3)) * 4 + 1 + rc0;   // rr=gid+8
            split_tf32(v2, vh, vl); s_mA[addr] = vh; s_mAl[addr] = vl;
            addr = tileBase + (gid * 4 + (cc1 & 3)) * 4 + 1 + rc1;
            split_tf32(v3, vh, vl); s_mA[addr] = vh; s_mAl[addr] = vl;
        }
    __syncthreads();

    // ---- layer 2 MMA: D2[c][j2] over kc = 0..31 ----
#pragma unroll
    for (int mt = 0; mt < 2; mt++)
#pragma unroll
        for (int nt = 0; nt < 4; nt++)
#pragma unroll
            for (int e = 0; e < 4; e++) acc[mt][nt][e] = 0.f;

#pragma unroll 2
    for (int kc = 0; kc < 32; kc++) {
        const uint4 ah0 = *(const uint4*)&s_mA[kc * 128 + lane * 4];
        const uint4 al0 = *(const uint4*)&s_mAl[kc * 128 + lane * 4];
        const uint4 ah1 = *(const uint4*)&s_mA[(32 + kc) * 128 + lane * 4];
        const uint4 al1 = *(const uint4*)&s_mAl[(32 + kc) * 128 + lane * 4];
#pragma unroll
        for (int nt = 0; nt < 4; nt++) {
            const uint4 bf = __ldg(&g_awf2[(kc * 32 + 4 * w + nt) * 32 + lane]);
            hmma_tf32(acc[0][nt], ah0, bf.x, bf.y);
            hmma_tf32(acc[0][nt], ah0, bf.z, bf.w);
            hmma_tf32(acc[0][nt], al0, bf.x, bf.y);
            hmma_tf32(acc[1][nt], ah1, bf.x, bf.y);
            hmma_tf32(acc[1][nt], ah1, bf.z, bf.w);
            hmma_tf32(acc[1][nt], al1, bf.x, bf.y);
        }
    }

    // ---- layer 3: tanh * w3, reduce over j ----
    {
        float pc[2][2] = {{0.f, 0.f}, {0.f, 0.f}};
#pragma unroll
        for (int mt = 0; mt < 2; mt++)
#pragma unroll
            for (int nt = 0; nt < 4; nt++) {
                pc[mt][0] += tanhf(acc[mt][nt][0] + bj2v[nt][0]) * w3j[nt][0]
                           + tanhf(acc[mt][nt][1] + bj2v[nt][1]) * w3j[nt][1];
                pc[mt][1] += tanhf(acc[mt][nt][2] + bj2v[nt][0]) * w3j[nt][0]
                           + tanhf(acc[mt][nt][3] + bj2v[nt][1]) * w3j[nt][1];
            }
#pragma unroll
        for (int mt = 0; mt < 2; mt++)
#pragma unroll
            for (int rh = 0; rh < 2; rh++) {
                float v = pc[mt][rh];
                v += __shfl_xor_sync(0xffffffffu, v, 1);
                v += __shfl_xor_sync(0xffffffffu, v, 2);
                pc[mt][rh] = v;
            }
        if (tig == 0) {
            s_red[w * 32 + 0 * 16 + gid]     = pc[0][0];
            s_red[w * 32 + 0 * 16 + gid + 8] = pc[0][1];
            s_red[w * 32 + 1 * 16 + gid]     = pc[1][0];
            s_red[w * 32 + 1 * 16 + gid + 8] = pc[1][1];
        }
    }
    __syncthreads();
    if (tid < CC) {
        float s = ab3[0];
#pragma unroll
        for (int ww = 0; ww < 8; ww++) s += s_red[ww * 32 + tid];
        if (tid < nvalid) g_scores[b][c0 + tid] = s;
    }
}

// ---------------------------------------------------------------------------
// K3: critic + masked softmax (proven).
// ---------------------------------------------------------------------------
__global__ __launch_bounds__(256) void k_final(
    const unsigned char* __restrict__ mask,
    const float* __restrict__ cw1, const float* __restrict__ cb1,
    const float* __restrict__ cw2, const float* __restrict__ cb2,
    const float* __restrict__ cw3, const float* __restrict__ cb3,
    float* __restrict__ out)
{
    __shared__ float s_in[HA];
    __shared__ float s_hid[HA];
    __shared__ float s_r[8];
    __shared__ float s_b0, s_b1v;

    const int tid = threadIdx.x, b = blockIdx.x;
    const int lane = tid & 31, warp = tid >> 5;

    s_in[tid] = g_pooled[b][tid];
    __syncthreads();
    float acc = cb1[tid];
    for (int i = 0; i < HA; i++) acc = fmaf(s_in[i], cw1[i * HA + tid], acc);
    s_hid[tid] = tanhf(acc);
    __syncthreads();
    acc = cb2[tid];
    for (int i = 0; i < HA; i++) acc = fmaf(s_hid[i], cw2[i * HA + tid], acc);
    {
        float p = tanhf(acc) * cw3[tid];
        p += __shfl_xor_sync(0xffffffffu, p, 16);
        p += __shfl_xor_sync(0xffffffffu, p, 8);
        p += __shfl_xor_sync(0xffffffffu, p, 4);
        p += __shfl_xor_sync(0xffffffffu, p, 2);
        p += __shfl_xor_sync(0xffffffffu, p, 1);
        if (lane == 0) s_r[warp] = p;
    }
    __syncthreads();
    if (tid == 0) {
        float v = cb3[0];
#pragma unroll
        for (int w = 0; w < 8; w++) v += s_r[w];
        out[BATCH * NC + b] = v;
    }

    const int c = tid;
    bool valid = false;
    float s = -FLT_MAX;
    if (c < NC) {
        const int mi = b * NC + c;
        const int mv = g_mask_i32 ? ((const int*)mask)[mi] : (int)mask[mi];
        valid = (mv != 0);
        if (valid) s = g_scores[b][c];
    }
    float m = s;
    m = fmaxf(m, __shfl_xor_sync(0xffffffffu, m, 16));
    m = fmaxf(m, __shfl_xor_sync(0xffffffffu, m, 8));
    m = fmaxf(m, __shfl_xor_sync(0xffffffffu, m, 4));
    m = fmaxf(m, __shfl_xor_sync(0xffffffffu, m, 2));
    m = fmaxf(m, __shfl_xor_sync(0xffffffffu, m, 1));
    __syncthreads();
    if (lane == 0) s_r[warp] = m;
    __syncthreads();
    if (warp == 0) {
        float t = (lane < 8) ? s_r[lane] : -FLT_MAX;
        t = fmaxf(t, __shfl_xor_sync(0xffffffffu, t, 4));
        t = fmaxf(t, __shfl_xor_sync(0xffffffffu, t, 2));
        t = fmaxf(t, __shfl_xor_sync(0xffffffffu, t, 1));
        if (lane == 0) s_b0 = t;
    }
    __syncthreads();
    const float mx = s_b0;
    const float e = valid ? expf(s - mx) : 0.f;
    float se = e;
    se += __shfl_xor_sync(0xffffffffu, se, 16);
    se += __shfl_xor_sync(0xffffffffu, se, 8);
    se += __shfl_xor_sync(0xffffffffu, se, 4);
    se += __shfl_xor_sync(0xffffffffu, se, 2);
    se += __shfl_xor_sync(0xffffffffu, se, 1);
    __syncthreads();
    if (lane == 0) s_r[warp] = se;
    __syncthreads();
    if (warp == 0) {
        float t = (lane < 8) ? s_r[lane] : 0.f;
        t += __shfl_xor_sync(0xffffffffu, t, 4);
        t += __shfl_xor_sync(0xffffffffu, t, 2);
        t += __shfl_xor_sync(0xffffffffu, t, 1);
        if (lane == 0) s_b1v = t;
    }
    __syncthreads();
    if (c < NC) out[b * NC + c] = e / s_b1v;
}

// ---------------------------------------------------------------------------
extern "C" void kernel_launch(void* const* d_in, const int* in_sizes, int n_in,
                              void* d_out, int out_size)
{
    const float* x    = (const float*)d_in[0];
    const int*   cand = (const int*)d_in[1];
    const unsigned char* mask = (const unsigned char*)d_in[2];
    const float* fw1 = (const float*)d_in[3];
    const float* fb1 = (const float*)d_in[4];
    const float* fw2 = (const float*)d_in[5];
    const float* fb2 = (const float*)d_in[6];
    const float* aw1 = (const float*)d_in[7];
    const float* ab1 = (const float*)d_in[8];
    const float* aw2 = (const float*)d_in[9];
    const float* ab2 = (const float*)d_in[10];
    const float* aw3 = (const float*)d_in[11];
    const float* ab3 = (const float*)d_in[12];
    const float* cw1 = (const float*)d_in[13];
    const float* cb1 = (const float*)d_in[14];
    const float* cw2 = (const float*)d_in[15];
    const float* cb2 = (const float*)d_in[16];
    const float* cw3 = (const float*)d_in[17];
    const float* cb3 = (const float*)d_in[18];
    float* out = (float*)d_out;

    const int smem_fp = 2 * 8192 * (int)sizeof(uint32_t);   // 64KB
    cudaFuncSetAttribute(k_featpool_wmma,
                         cudaFuncAttributeMaxDynamicSharedMemorySize, smem_fp);
    const int smem_actor = 27232 * (int)sizeof(uint32_t);   // 108928 B
    cudaFuncSetAttribute(k_actor_mma,
                         cudaFuncAttributeMaxDynamicSharedMemorySize, smem_actor);

    k_sniff<<<1, 32>>>(mask);
    k_wsplit<<<192, 256>>>(aw1, aw2);
    k_featpool_wmma<<<dim3(NCH, BATCH), 256, smem_fp>>>(x, fw1, fb1, fw2, fb2);
    k_pool<<<BATCH, 256>>>(x, fw1, fb1, fw2, fb2, aw1);
    k_actor_mma<<<dim3(NCHUNK, BATCH), 256, smem_actor>>>(
        x, cand, fw1, fb1, fw2, fb2, ab1, ab2, aw3, ab3);
    k_final<<<BATCH, 256>>>(mask, cw1, cb1, cw2, cb2, cw3, cb3, out);
}

// round 11
// speedup vs baseline: 2.0816x; 1.5015x over previous
#include <cuda_runtime.h>
#include <cuda_bf16.h>
#include <math.h>
#include <float.h>
#include <stdint.h>

// Problem dims
#define BATCH 64
#define NN    10000
#define NC    201
#define H     64
#define ND    128      // node feature dim (2H)
#define HA    256      // actor/critic hidden
#define NCH   6        // chunks per batch (wmma featpool)
#define TPT   13       // 128-node tiles per chunk (6*13*128 = 9984)
#define NTAIL 16       // tail nodes handled in k_pool
#define CC    32       // candidates per actor block
#define NCHUNK 7       // ceil(201/32)

// Scratch (device globals: no allocation allowed)
__device__ float g_psum[BATCH][NCH][ND];
__device__ float g_pmax[BATCH][NCH][ND];
__device__ float g_pooled[BATCH][2 * ND];
__device__ float g_pproj[BATCH][HA];
__device__ float g_scores[BATCH][NC];
__device__ int   g_mask_i32;
// Pre-split bf16 fragment-packed actor weights: (bh0, bh1, bl0, bl1) per lane.
__device__ uint4 g_awf1[8 * 32 * 32];    // [kc 8][ntg 32][lane 32]   (k=128)
__device__ uint4 g_awf2[16 * 32 * 32];   // [kc 16][ntg 32][lane 32]  (k=256)

// ---- f32x2 packed helpers ----
static __device__ __forceinline__ unsigned long long dup2(float w) {
    unsigned long long r;
    unsigned int b = __float_as_uint(w);
    asm("mov.b64 %0, {%1, %1};" : "=l"(r) : "r"(b));
    return r;
}
static __device__ __forceinline__ unsigned long long pk2(float lo, float hi) {
    unsigned long long r;
    unsigned int a = __float_as_uint(lo), b = __float_as_uint(hi);
    asm("mov.b64 %0, {%1, %2};" : "=l"(r) : "r"(a), "r"(b));
    return r;
}
static __device__ __forceinline__ unsigned long long fma2(
    unsigned long long a, unsigned long long b, unsigned long long c) {
    unsigned long long d;
    asm("fma.rn.f32x2 %0, %1, %2, %3;" : "=l"(d) : "l"(a), "l"(b), "l"(c));
    return d;
}
static __device__ __forceinline__ void unpack2(unsigned long long v, float& lo, float& hi) {
    unsigned int a, b;
    asm("mov.b64 {%0, %1}, %2;" : "=r"(a), "=r"(b) : "l"(v));
    lo = __uint_as_float(a);
    hi = __uint_as_float(b);
}

// ---- bf16 split/pack + warp-MMA helpers (sm_80+ generic) ----
static __device__ __forceinline__ void split_bf16(float f, __nv_bfloat16& h, __nv_bfloat16& l) {
    h = __float2bfloat16_rn(f);
    l = __float2bfloat16_rn(f - __bfloat162float(h));
}
static __device__ __forceinline__ uint32_t pack_bf162(__nv_bfloat16 e0, __nv_bfloat16 e1) {
    __nv_bfloat162 v = __halves2bfloat162(e0, e1);   // .x = e0 (low 16 bits)
    return *reinterpret_cast<uint32_t*>(&v);
}
// split two floats, return (hiPack, loPack) where element order = (f0, f1)
static __device__ __forceinline__ void split_pack2(float f0, float f1,
                                                   uint32_t& hp, uint32_t& lp) {
    __nv_bfloat16 h0, l0, h1, l1;
    split_bf16(f0, h0, l0);
    split_bf16(f1, h1, l1);
    hp = pack_bf162(h0, h1);
    lp = pack_bf162(l0, l1);
}
static __device__ __forceinline__ void hmma_bf16(
    float* d, const uint4& a, uint32_t b0, uint32_t b1) {
    asm volatile(
        "mma.sync.aligned.m16n8k16.row.col.f32.bf16.bf16.f32 "
        "{%0,%1,%2,%3}, {%4,%5,%6,%7}, {%8,%9}, {%0,%1,%2,%3};"
        : "+f"(d[0]), "+f"(d[1]), "+f"(d[2]), "+f"(d[3])
        : "r"(a.x), "r"(a.y), "r"(a.z), "r"(a.w), "r"(b0), "r"(b1));
}

// ---------------------------------------------------------------------------
// K0: sniff mask dtype.
// ---------------------------------------------------------------------------
__global__ void k_sniff(const unsigned char* __restrict__ m) {
    if (threadIdx.x == 0) {
        int any = 0;
        for (int i = 0; i < 1024; i++)
            if ((i & 3) && m[i]) any = 1;
        g_mask_i32 = any ? 0 : 1;
    }
}

// ---------------------------------------------------------------------------
// K0b: pre-split actor weights into bf16 fragment-packed hi/lo.
// B frag m16n8k16: b0 = {B[2t][g], B[2t+1][g]}, b1 = {B[2t+8][g], B[2t+9][g]}.
// ---------------------------------------------------------------------------
__global__ __launch_bounds__(256) void k_wsplit(
    const float* __restrict__ aw1, const float* __restrict__ aw2)
{
    const int t = blockIdx.x * 256 + threadIdx.x;
    const int n1 = 8 * 32 * 32;
    if (t < n1) {
        const int lane = t & 31, ntg = (t >> 5) & 31, kc = t >> 10;
        const int g = lane >> 2, tg = lane & 3;
        const int j = ntg * 8 + g;
        const int k0 = kc * 16 + 2 * tg;
        __nv_bfloat16 h00, l00, h01, l01, h10, l10, h11, l11;
        split_bf16(aw1[(k0 + 0) * HA + j], h00, l00);
        split_bf16(aw1[(k0 + 1) * HA + j], h01, l01);
        split_bf16(aw1[(k0 + 8) * HA + j], h10, l10);
        split_bf16(aw1[(k0 + 9) * HA + j], h11, l11);
        uint4 v;
        v.x = pack_bf162(h00, h01);
        v.y = pack_bf162(h10, h11);
        v.z = pack_bf162(l00, l01);
        v.w = pack_bf162(l10, l11);
        g_awf1[t] = v;
    } else {
        const int t2 = t - n1;
        if (t2 >= 16 * 32 * 32) return;
        const int lane = t2 & 31, ntg = (t2 >> 5) & 31, kc = t2 >> 10;
        const int g = lane >> 2, tg = lane & 3;
        const int j = ntg * 8 + g;
        const int k0 = kc * 16 + 2 * tg;
        __nv_bfloat16 h00, l00, h01, l01, h10, l10, h11, l11;
        split_bf16(aw2[(k0 + 0) * HA + j], h00, l00);
        split_bf16(aw2[(k0 + 1) * HA + j], h01, l01);
        split_bf16(aw2[(k0 + 8) * HA + j], h10, l10);
        split_bf16(aw2[(k0 + 9) * HA + j], h11, l11);
        uint4 v;
        v.x = pack_bf162(h00, h01);
        v.y = pack_bf162(h10, h11);
        v.z = pack_bf162(l00, l01);
        v.w = pack_bf162(l10, l11);
        g_awf2[t2] = v;
    }
}

// ---------------------------------------------------------------------------
// K1: featpool via 3-term bf16 split MMA (m16n8k16): AhBh + AhBl + AlBh.
// Warp w owns d-columns [16w, 16w+16) (2 n-tiles). Per 128-node tile:
// layer-1 writes h split/packed into A-fragment layout; 8mt x 4kc x 2nt x 3
// HMMA; relu(D+b2) pooling fold (D layout identical to tf32 version).
// ---------------------------------------------------------------------------
__global__ __launch_bounds__(256) void k_featpool_wmma(
    const float* __restrict__ x,
    const float* __restrict__ w1, const float* __restrict__ b1,
    const float* __restrict__ w2, const float* __restrict__ b2)
{
    extern __shared__ __align__(16) uint32_t s_dyn[];
    uint32_t* s_Ah = s_dyn;            // 8mt*4kc*128 = 4096 u32 (16KB)
    uint32_t* s_Al = s_dyn + 4096;     // 16KB
    __shared__ __align__(16) float4 s_x4[128];
    __shared__ __align__(16) float s_w1t[H][4];

    const int tid = threadIdx.x;
    const int wid = tid >> 5, lane = tid & 31;
    const int b = blockIdx.y, chunk = blockIdx.x;
    const int base = chunk * TPT * 128;
    const int tig = lane & 3;
    const int gid = lane >> 2;

    if (tid < H) {
        s_w1t[tid][0] = w1[tid];
        s_w1t[tid][1] = w1[H + tid];
        s_w1t[tid][2] = w1[2 * H + tid];
        s_w1t[tid][3] = b1[tid];
    }

    // B fragments: w2[k][d] (k-major). Per (kc 4, nt 2): 2 hi + 2 lo regs.
    uint32_t Bh[4][2][2], Bl[4][2][2];
#pragma unroll
    for (int kc = 0; kc < 4; kc++)
#pragma unroll
        for (int nt = 0; nt < 2; nt++) {
            const int d = 16 * wid + nt * 8 + gid;
            const int k0 = kc * 16 + 2 * tig;
            __nv_bfloat16 h0, l0, h1, l1;
            split_bf16(__ldg(w2 + (k0 + 0) * ND + d), h0, l0);
            split_bf16(__ldg(w2 + (k0 + 1) * ND + d), h1, l1);
            Bh[kc][nt][0] = pack_bf162(h0, h1);
            Bl[kc][nt][0] = pack_bf162(l0, l1);
            split_bf16(__ldg(w2 + (k0 + 8) * ND + d), h0, l0);
            split_bf16(__ldg(w2 + (k0 + 9) * ND + d), h1, l1);
            Bh[kc][nt][1] = pack_bf162(h0, h1);
            Bl[kc][nt][1] = pack_bf162(l0, l1);
        }

    float bcol[2][2];
#pragma unroll
    for (int nt = 0; nt < 2; nt++) {
        const int d0 = 16 * wid + nt * 8 + 2 * tig;
        bcol[nt][0] = b2[d0];
        bcol[nt][1] = b2[d0 + 1];
    }

    float psum[2][4], pmax[2][4];
#pragma unroll
    for (int nt = 0; nt < 2; nt++)
#pragma unroll
        for (int e = 0; e < 4; e++) { psum[nt][e] = 0.f; pmax[nt][e] = 0.f; }

    __syncthreads();

    for (int t = 0; t < TPT; t++) {
        if (tid < 128) {
            const int node = base + t * 128 + tid;
            const float* xp = x + ((long)b * NN + node) * 3;
            s_x4[tid] = make_float4(xp[0], xp[1], xp[2], 0.f);
        }
        __syncthreads();

        // layer-1 into bf16 A-fragment layout: 16 slots per thread.
        // slot -> r (reg 0..3), ln (lane), kc (0..3), mt (0..7)
        // A frag: row = g + (r&1)*8, kpair base = 2t + ((r>>1)&1)*8
#pragma unroll
        for (int q = 0; q < 16; q++) {
            const int s = q * 256 + tid;
            const int r = s & 3;
            const int ln = (s >> 2) & 31;
            const int kc = (s >> 7) & 3;
            const int mt = s >> 9;
            const int row = mt * 16 + (ln >> 2) + (r & 1) * 8;
            const int k0 = kc * 16 + 2 * (ln & 3) + ((r >> 1) & 1) * 8;
            const float4 xv = s_x4[row];
            const float4 wa = *(const float4*)&s_w1t[k0][0];
            const float4 wb = *(const float4*)&s_w1t[k0 + 1][0];
            const float h0 = fmaxf(fmaf(xv.x, wa.x, fmaf(xv.y, wa.y, fmaf(xv.z, wa.z, wa.w))), 0.f);
            const float h1 = fmaxf(fmaf(xv.x, wb.x, fmaf(xv.y, wb.y, fmaf(xv.z, wb.z, wb.w))), 0.f);
            uint32_t hp, lp;
            split_pack2(h0, h1, hp, lp);
            const int addr = (mt * 4 + kc) * 128 + ln * 4 + r;
            s_Ah[addr] = hp;
            s_Al[addr] = lp;
        }
        __syncthreads();

        // MMA (3-term bf16) + pooling fold (D layout same as before)
        for (int mt = 0; mt < 8; mt++) {
            float d[2][4];
#pragma unroll
            for (int nt = 0; nt < 2; nt++)
#pragma unroll
                for (int e = 0; e < 4; e++) d[nt][e] = 0.f;
#pragma unroll
            for (int kc = 0; kc < 4; kc++) {
                const int off = (mt * 4 + kc) * 128 + lane * 4;
                const uint4 ah = *(const uint4*)&s_Ah[off];
                const uint4 al = *(const uint4*)&s_Al[off];
#pragma unroll
                for (int nt = 0; nt < 2; nt++) {
                    hmma_bf16(d[nt], ah, Bh[kc][nt][0], Bh[kc][nt][1]);
                    hmma_bf16(d[nt], ah, Bl[kc][nt][0], Bl[kc][nt][1]);
                    hmma_bf16(d[nt], al, Bh[kc][nt][0], Bh[kc][nt][1]);
                }
            }
#pragma unroll
            for (int nt = 0; nt < 2; nt++) {
                const float y0 = fmaxf(d[nt][0] + bcol[nt][0], 0.f);
                const float y1 = fmaxf(d[nt][1] + bcol[nt][1], 0.f);
                const float y2 = fmaxf(d[nt][2] + bcol[nt][0], 0.f);
                const float y3 = fmaxf(d[nt][3] + bcol[nt][1], 0.f);
                psum[nt][0] += y0; pmax[nt][0] = fmaxf(pmax[nt][0], y0);
                psum[nt][1] += y1; pmax[nt][1] = fmaxf(pmax[nt][1], y1);
                psum[nt][2] += y2; pmax[nt][2] = fmaxf(pmax[nt][2], y2);
                psum[nt][3] += y3; pmax[nt][3] = fmaxf(pmax[nt][3], y3);
            }
        }
    }

#pragma unroll
    for (int nt = 0; nt < 2; nt++) {
        float sc0 = psum[nt][0] + psum[nt][2];
        float sc1 = psum[nt][1] + psum[nt][3];
        float mc0 = fmaxf(pmax[nt][0], pmax[nt][2]);
        float mc1 = fmaxf(pmax[nt][1], pmax[nt][3]);
#pragma unroll
        for (int ofs = 4; ofs <= 16; ofs <<= 1) {
            sc0 += __shfl_xor_sync(0xffffffffu, sc0, ofs);
            sc1 += __shfl_xor_sync(0xffffffffu, sc1, ofs);
            mc0 = fmaxf(mc0, __shfl_xor_sync(0xffffffffu, mc0, ofs));
            mc1 = fmaxf(mc1, __shfl_xor_sync(0xffffffffu, mc1, ofs));
        }
        if (lane < 4) {
            const int d0 = 16 * wid + nt * 8 + 2 * lane;
            g_psum[b][chunk][d0]     = sc0;
            g_psum[b][chunk][d0 + 1] = sc1;
            g_pmax[b][chunk][d0]     = mc0;
            g_pmax[b][chunk][d0 + 1] = mc1;
        }
    }
}

// ---------------------------------------------------------------------------
// K1b: fp32 tail + combine partials -> pooled + pproj (proven).
// ---------------------------------------------------------------------------
__global__ __launch_bounds__(256) void k_pool(
    const float* __restrict__ x,
    const float* __restrict__ fw1, const float* __restrict__ fb1,
    const float* __restrict__ fw2, const float* __restrict__ fb2,
    const float* __restrict__ aw1)
{
    __shared__ float s_h[NTAIL * H];
    __shared__ float s_ts[2][ND];
    __shared__ float s_tm[2][ND];
    __shared__ float s_pool[2 * ND];

    const int b = blockIdx.x, tid = threadIdx.x;

#pragma unroll
    for (int i = 0; i < 4; i++) {
        const int v = tid + i * 256;
        const int n = v >> 6, k = v & 63;
        const float* xp = x + ((long)b * NN + (NN - NTAIL) + n) * 3;
        const float h = fmaf(xp[0], fw1[k],
                        fmaf(xp[1], fw1[H + k],
                        fmaf(xp[2], fw1[2 * H + k], fb1[k])));
        s_h[n * H + k] = fmaxf(h, 0.f);
    }
    __syncthreads();

    {
        const int d = tid & 127, half = tid >> 7;
        float ts = 0.f, tm = 0.f;
        for (int n = half * 8; n < half * 8 + 8; n++) {
            float a = fb2[d];
            for (int k = 0; k < H; k++)
                a = fmaf(s_h[n * H + k], __ldg(fw2 + k * ND + d), a);
            const float y = fmaxf(a, 0.f);
            ts += y;
            tm = fmaxf(tm, y);
        }
        s_ts[half][d] = ts;
        s_tm[half][d] = tm;
    }
    __syncthreads();

    if (tid < ND) {
        float s = s_ts[0][tid] + s_ts[1][tid];
        float m = fmaxf(s_tm[0][tid], s_tm[1][tid]);
#pragma unroll
        for (int ch = 0; ch < NCH; ch++) {
            s += g_psum[b][ch][tid];
            m = fmaxf(m, g_pmax[b][ch][tid]);
        }
        const float mean = s * (1.f / NN);
        g_pooled[b][tid] = mean;
        g_pooled[b][ND + tid] = m;
        s_pool[tid] = mean;
        s_pool[ND + tid] = m;
    }
    __syncthreads();

    float pc = 0.f;
    for (int i = 0; i < 2 * ND; i++)
        pc = fmaf(s_pool[i], __ldg(aw1 + (ND + i) * HA + tid), pc);
    g_pproj[b][tid] = pc;
}

// ---------------------------------------------------------------------------
// K2: actor via 3-term bf16 split MMA (m16n8k16).
// Warp w owns n-tiles ntg = 4w..4w+3. m = 32 candidates = 2 m-tiles.
// Layer-1 k = 128 (8 kc), layer-2 k = 256 (16 kc). A frags in smem hi/lo;
// B frags from pre-split packed globals. Epilogue D (c, 2t/2t+1) pairs pack
// directly into the next layer's bf16x2 A k-pairs.
// Dyn smem (u32): fA 2048 | fAl 2048 | mA 4096 | mAl 4096 | hT 2048f |
//                 x 96f | w1t 256f | red 256f = 14944 u32 = 59776 B.
// ---------------------------------------------------------------------------
__global__ __launch_bounds__(256, 2) void k_actor_mma(
    const float* __restrict__ x, const int* __restrict__ cand,
    const float* __restrict__ fw1, const float* __restrict__ fb1,
    const float* __restrict__ fw2, const float* __restrict__ fb2,
    const float* __restrict__ ab1, const float* __restrict__ ab2,
    const float* __restrict__ aw3, const float* __restrict__ ab3)
{
    extern __shared__ __align__(16) uint32_t sA[];
    uint32_t* s_fA  = sA;              // 2048
    uint32_t* s_fAl = sA + 2048;       // 2048
    uint32_t* s_mA  = sA + 4096;       // 4096
    uint32_t* s_mAl = sA + 8192;       // 4096
    float* s_hT  = (float*)(sA + 12288);   // 2048 (64 k x 32 c)
    float* s_x   = s_hT + 2048;            // 96
    float* s_w1t = s_x + 96;               // 256
    float* s_red = s_w1t + 256;            // 256

    const int tid = threadIdx.x;
    const int w = tid >> 5, lane = tid & 31;
    const int gid = lane >> 2, tig = lane & 3;
    const int b = blockIdx.y;
    const int c0 = blockIdx.x * CC;
    const int nvalid = min(CC, NC - c0);

    if (tid < H) {
        s_w1t[tid * 4 + 0] = fw1[tid];
        s_w1t[tid * 4 + 1] = fw1[H + tid];
        s_w1t[tid * 4 + 2] = fw1[2 * H + tid];
        s_w1t[tid * 4 + 3] = fb1[tid];
    }
    if (tid < CC * 3) {
        const int c = tid / 3, i = tid - c * 3;
        float v = 0.f;
        if (c < nvalid) {
            const int node = cand[b * NC + c0 + c];
            v = x[((long)b * NN + node) * 3 + i];
        }
        s_x[tid] = v;
    }
    __syncthreads();

    // fe layer 1 -> s_hT[k][c]
    {
        const int n1 = tid & 31, kg = tid >> 5;
        const float x0 = s_x[n1 * 3 + 0];
        const float x1 = s_x[n1 * 3 + 1];
        const float x2 = s_x[n1 * 3 + 2];
#pragma unroll
        for (int m = 0; m < 8; m++) {
            const int k = kg * 8 + m;
            const float4 wv = *(const float4*)&s_w1t[k * 4];
            const float v = fmaf(x0, wv.x, fmaf(x1, wv.y, fmaf(x2, wv.z, wv.w)));
            s_hT[k * CC + n1] = fmaxf(v, 0.f);
        }
    }
    __syncthreads();

    // fe layer 2 -> feat fragments. Thread = (dg = tid&63 -> d0=2dg,d1; qh = tid>>6
    // -> 8 candidates c = qh*8+i). acc packs (d0,d1) per c via f32x2.
    {
        const int dg = tid & 63, qh = tid >> 6;
        const int d0 = 2 * dg;
        unsigned long long a2[8];
#pragma unroll
        for (int i = 0; i < 8; i++) a2[i] = 0ull;
#pragma unroll 4
        for (int k = 0; k < H; k++) {
            const float2 wp = __ldg((const float2*)(fw2 + k * ND + d0));
            const unsigned long long wpk = pk2(wp.x, wp.y);
            const float4 hA = *(const float4*)(s_hT + k * CC + qh * 8);
            const float4 hB = *(const float4*)(s_hT + k * CC + qh * 8 + 4);
            a2[0] = fma2(dup2(hA.x), wpk, a2[0]);
            a2[1] = fma2(dup2(hA.y), wpk, a2[1]);
            a2[2] = fma2(dup2(hA.z), wpk, a2[2]);
            a2[3] = fma2(dup2(hA.w), wpk, a2[3]);
            a2[4] = fma2(dup2(hB.x), wpk, a2[4]);
            a2[5] = fma2(dup2(hB.y), wpk, a2[5]);
            a2[6] = fma2(dup2(hB.z), wpk, a2[6]);
            a2[7] = fma2(dup2(hB.w), wpk, a2[7]);
        }
        const float b20 = fb2[d0], b21 = fb2[d0 + 1];
        const int kc = d0 >> 4;
        const int t2 = (d0 >> 1) & 3;
        const int r2 = ((d0 >> 3) & 1) * 2;
#pragma unroll
        for (int i = 0; i < 8; i++) {
            const int c = qh * 8 + i;
            float lo, hi;
            unpack2(a2[i], lo, hi);
            const float y0 = fmaxf(lo + b20, 0.f);
            const float y1 = fmaxf(hi + b21, 0.f);
            uint32_t hp, lp;
            split_pack2(y0, y1, hp, lp);
            const int rit = c & 15;
            const int addr = ((c >> 4) * 8 + kc) * 128 +
                             ((rit & 7) * 4 + t2) * 4 + (rit >> 3) + r2;
            s_fA[addr] = hp;
            s_fAl[addr] = lp;
        }
    }

    float bj1[4][2], bj2v[4][2], w3j[4][2];
#pragma unroll
    for (int nt = 0; nt < 4; nt++) {
        const int j0 = (4 * w + nt) * 8 + 2 * tig;
        bj1[nt][0] = ab1[j0] + g_pproj[b][j0];
        bj1[nt][1] = ab1[j0 + 1] + g_pproj[b][j0 + 1];
        bj2v[nt][0] = ab2[j0];     bj2v[nt][1] = ab2[j0 + 1];
        w3j[nt][0] = aw3[j0];      w3j[nt][1] = aw3[j0 + 1];
    }
    __syncthreads();

    float acc[2][4][4];

    // ---- layer 1 MMA: kc = 0..7 ----
#pragma unroll
    for (int mt = 0; mt < 2; mt++)
#pragma unroll
        for (int nt = 0; nt < 4; nt++)
#pragma unroll
            for (int e = 0; e < 4; e++) acc[mt][nt][e] = 0.f;

#pragma unroll 2
    for (int kc = 0; kc < 8; kc++) {
        const uint4 ah0 = *(const uint4*)&s_fA[kc * 128 + lane * 4];
        const uint4 al0 = *(const uint4*)&s_fAl[kc * 128 + lane * 4];
        const uint4 ah1 = *(const uint4*)&s_fA[(8 + kc) * 128 + lane * 4];
        const uint4 al1 = *(const uint4*)&s_fAl[(8 + kc) * 128 + lane * 4];
#pragma unroll
        for (int nt = 0; nt < 4; nt++) {
            const uint4 bf = __ldg(&g_awf1[(kc * 32 + 4 * w + nt) * 32 + lane]);
            hmma_bf16(acc[0][nt], ah0, bf.x, bf.y);
            hmma_bf16(acc[0][nt], ah0, bf.z, bf.w);
            hmma_bf16(acc[0][nt], al0, bf.x, bf.y);
            hmma_bf16(acc[1][nt], ah1, bf.x, bf.y);
            hmma_bf16(acc[1][nt], ah1, bf.z, bf.w);
            hmma_bf16(acc[1][nt], al1, bf.x, bf.y);
        }
    }

    // layer-1 epilogue: tanh -> mid fragments (D (c, j0/j0+1) packs one k-pair)
#pragma unroll
    for (int mt = 0; mt < 2; mt++)
#pragma unroll
        for (int nt = 0; nt < 4; nt++) {
            const int ntg = 4 * w + nt;
            const int kc2 = ntg >> 1;
            const int r2 = (ntg & 1) * 2;
            const int base = (mt * 16 + kc2) * 128 + (gid * 4 + tig) * 4 + r2;
            const float v0 = tanhf(acc[mt][nt][0] + bj1[nt][0]);  // (c=mt*16+gid,   j0)
            const float v1 = tanhf(acc[mt][nt][1] + bj1[nt][1]);  // (c=mt*16+gid,   j0+1)
            const float v2 = tanhf(acc[mt][nt][2] + bj1[nt][0]);  // (c=mt*16+gid+8, j0)
            const float v3 = tanhf(acc[mt][nt][3] + bj1[nt][1]);
            uint32_t hp, lp;
            split_pack2(v0, v1, hp, lp);
            s_mA[base] = hp;     s_mAl[base] = lp;
            split_pack2(v2, v3, hp, lp);
            s_mA[base + 1] = hp; s_mAl[base + 1] = lp;
        }
    __syncthreads();

    // ---- layer 2 MMA: kc2 = 0..15 ----
#pragma unroll
    for (int mt = 0; mt < 2; mt++)
#pragma unroll
        for (int nt = 0; nt < 4; nt++)
#pragma unroll
            for (int e = 0; e < 4; e++) acc[mt][nt][e] = 0.f;

#pragma unroll 2
    for (int kc = 0; kc < 16; kc++) {
        const uint4 ah0 = *(const uint4*)&s_mA[kc * 128 + lane * 4];
        const uint4 al0 = *(const uint4*)&s_mAl[kc * 128 + lane * 4];
        const uint4 ah1 = *(const uint4*)&s_mA[(16 + kc) * 128 + lane * 4];
        const uint4 al1 = *(const uint4*)&s_mAl[(16 + kc) * 128 + lane * 4];
#pragma unroll
        for (int nt = 0; nt < 4; nt++) {
            const uint4 bf = __ldg(&g_awf2[(kc * 32 + 4 * w + nt) * 32 + lane]);
            hmma_bf16(acc[0][nt], ah0, bf.x, bf.y);
            hmma_bf16(acc[0][nt], ah0, bf.z, bf.w);
            hmma_bf16(acc[0][nt], al0, bf.x, bf.y);
            hmma_bf16(acc[1][nt], ah1, bf.x, bf.y);
            hmma_bf16(acc[1][nt], ah1, bf.z, bf.w);
            hmma_bf16(acc[1][nt], al1, bf.x, bf.y);
        }
    }

    // ---- layer 3 ----
    {
        float pc[2][2] = {{0.f, 0.f}, {0.f, 0.f}};
#pragma unroll
        for (int mt = 0; mt < 2; mt++)
#pragma unroll
            for (int nt = 0; nt < 4; nt++) {
                pc[mt][0] += tanhf(acc[mt][nt][0] + bj2v[nt][0]) * w3j[nt][0]
                           + tanhf(acc[mt][nt][1] + bj2v[nt][1]) * w3j[nt][1];
                pc[mt][1] += tanhf(acc[mt][nt][2] + bj2v[nt][0]) * w3j[nt][0]
                           + tanhf(acc[mt][nt][3] + bj2v[nt][1]) * w3j[nt][1];
            }
#pragma unroll
        for (int mt = 0; mt < 2; mt++)
#pragma unroll
            for (int rh = 0; rh < 2; rh++) {
                float v = pc[mt][rh];
                v += __shfl_xor_sync(0xffffffffu, v, 1);
                v += __shfl_xor_sync(0xffffffffu, v, 2);
                pc[mt][rh] = v;
            }
        if (tig == 0) {
            s_red[w * 32 + 0 * 16 + gid]     = pc[0][0];
            s_red[w * 32 + 0 * 16 + gid + 8] = pc[0][1];
            s_red[w * 32 + 1 * 16 + gid]     = pc[1][0];
            s_red[w * 32 + 1 * 16 + gid + 8] = pc[1][1];
        }
    }
    __syncthreads();
    if (tid < CC) {
        float s = ab3[0];
#pragma unroll
        for (int ww = 0; ww < 8; ww++) s += s_red[ww * 32 + tid];
        if (tid < nvalid) g_scores[b][c0 + tid] = s;
    }
}

// ---------------------------------------------------------------------------
// K3: critic + masked softmax (proven).
// ---------------------------------------------------------------------------
__global__ __launch_bounds__(256) void k_final(
    const unsigned char* __restrict__ mask,
    const float* __restrict__ cw1, const float* __restrict__ cb1,
    const float* __restrict__ cw2, const float* __restrict__ cb2,
    const float* __restrict__ cw3, const float* __restrict__ cb3,
    float* __restrict__ out)
{
    __shared__ float s_in[HA];
    __shared__ float s_hid[HA];
    __shared__ float s_r[8];
    __shared__ float s_b0, s_b1v;

    const int tid = threadIdx.x, b = blockIdx.x;
    const int lane = tid & 31, warp = tid >> 5;

    s_in[tid] = g_pooled[b][tid];
    __syncthreads();
    float acc = cb1[tid];
    for (int i = 0; i < HA; i++) acc = fmaf(s_in[i], cw1[i * HA + tid], acc);
    s_hid[tid] = tanhf(acc);
    __syncthreads();
    acc = cb2[tid];
    for (int i = 0; i < HA; i++) acc = fmaf(s_hid[i], cw2[i * HA + tid], acc);
    {
        float p = tanhf(acc) * cw3[tid];
        p += __shfl_xor_sync(0xffffffffu, p, 16);
        p += __shfl_xor_sync(0xffffffffu, p, 8);
        p += __shfl_xor_sync(0xffffffffu, p, 4);
        p += __shfl_xor_sync(0xffffffffu, p, 2);
        p += __shfl_xor_sync(0xffffffffu, p, 1);
        if (lane == 0) s_r[warp] = p;
    }
    __syncthreads();
    if (tid == 0) {
        float v = cb3[0];
#pragma unroll
        for (int w = 0; w < 8; w++) v += s_r[w];
        out[BATCH * NC + b] = v;
    }

    const int c = tid;
    bool valid = false;
    float s = -FLT_MAX;
    if (c < NC) {
        const int mi = b * NC + c;
        const int mv = g_mask_i32 ? ((const int*)mask)[mi] : (int)mask[mi];
        valid = (mv != 0);
        if (valid) s = g_scores[b][c];
    }
    float m = s;
    m = fmaxf(m, __shfl_xor_sync(0xffffffffu, m, 16));
    m = fmaxf(m, __shfl_xor_sync(0xffffffffu, m, 8));
    m = fmaxf(m, __shfl_xor_sync(0xffffffffu, m, 4));
    m = fmaxf(m, __shfl_xor_sync(0xffffffffu, m, 2));
    m = fmaxf(m, __shfl_xor_sync(0xffffffffu, m, 1));
    __syncthreads();
    if (lane == 0) s_r[warp] = m;
    __syncthreads();
    if (warp == 0) {
        float t = (lane < 8) ? s_r[lane] : -FLT_MAX;
        t = fmaxf(t, __shfl_xor_sync(0xffffffffu, t, 4));
        t = fmaxf(t, __shfl_xor_sync(0xffffffffu, t, 2));
        t = fmaxf(t, __shfl_xor_sync(0xffffffffu, t, 1));
        if (lane == 0) s_b0 = t;
    }
    __syncthreads();
    const float mx = s_b0;
    const float e = valid ? expf(s - mx) : 0.f;
    float se = e;
    se += __shfl_xor_sync(0xffffffffu, se, 16);
    se += __shfl_xor_sync(0xffffffffu, se, 8);
    se += __shfl_xor_sync(0xffffffffu, se, 4);
    se += __shfl_xor_sync(0xffffffffu, se, 2);
    se += __shfl_xor_sync(0xffffffffu, se, 1);
    __syncthreads();
    if (lane == 0) s_r[warp] = se;
    __syncthreads();
    if (warp == 0) {
        float t = (lane < 8) ? s_r[lane] : 0.f;
        t += __shfl_xor_sync(0xffffffffu, t, 4);
        t += __shfl_xor_sync(0xffffffffu, t, 2);
        t += __shfl_xor_sync(0xffffffffu, t, 1);
        if (lane == 0) s_b1v = t;
    }
    __syncthreads();
    if (c < NC) out[b * NC + c] = e / s_b1v;
}

// ---------------------------------------------------------------------------
extern "C" void kernel_launch(void* const* d_in, const int* in_sizes, int n_in,
                              void* d_out, int out_size)
{
    const float* x    = (const float*)d_in[0];
    const int*   cand = (const int*)d_in[1];
    const unsigned char* mask = (const unsigned char*)d_in[2];
    const float* fw1 = (const float*)d_in[3];
    const float* fb1 = (const float*)d_in[4];
    const float* fw2 = (const float*)d_in[5];
    const float* fb2 = (const float*)d_in[6];
    const float* aw1 = (const float*)d_in[7];
    const float* ab1 = (const float*)d_in[8];
    const float* aw2 = (const float*)d_in[9];
    const float* ab2 = (const float*)d_in[10];
    const float* aw3 = (const float*)d_in[11];
    const float* ab3 = (const float*)d_in[12];
    const float* cw1 = (const float*)d_in[13];
    const float* cb1 = (const float*)d_in[14];
    const float* cw2 = (const float*)d_in[15];
    const float* cb2 = (const float*)d_in[16];
    const float* cw3 = (const float*)d_in[17];
    const float* cb3 = (const float*)d_in[18];
    float* out = (float*)d_out;

    const int smem_fp = 2 * 4096 * (int)sizeof(uint32_t);   // 32KB
    cudaFuncSetAttribute(k_featpool_wmma,
                         cudaFuncAttributeMaxDynamicSharedMemorySize, smem_fp);
    const int smem_actor = 14944 * (int)sizeof(uint32_t);   // 59776 B
    cudaFuncSetAttribute(k_actor_mma,
                         cudaFuncAttributeMaxDynamicSharedMemorySize, smem_actor);

    k_sniff<<<1, 32>>>(mask);
    k_wsplit<<<96, 256>>>(aw1, aw2);
    k_featpool_wmma<<<dim3(NCH, BATCH), 256, smem_fp>>>(x, fw1, fb1, fw2, fb2);
    k_pool<<<BATCH, 256>>>(x, fw1, fb1, fw2, fb2, aw1);
    k_actor_mma<<<dim3(NCHUNK, BATCH), 256, smem_actor>>>(
        x, cand, fw1, fb1, fw2, fb2, ab1, ab2, aw3, ab3);
    k_final<<<BATCH, 256>>>(mask, cw1, cb1, cw2, cb2, cw3, cb3, out);
}

// round 12
// speedup vs baseline: 2.2801x; 1.0953x over previous
#include <cuda_runtime.h>
#include <cuda_bf16.h>
#include <math.h>
#include <float.h>
#include <stdint.h>

// Problem dims
#define BATCH 64
#define NN    10000
#define NC    201
#define H     64
#define ND    128      // node feature dim (2H)
#define HA    256      // actor/critic hidden
#define NCH   9        // chunks per batch (wmma featpool)
#define TPT   9        // 128-node tiles per chunk (9*9*128 = 10368 >= 10000, predicated)
#define CC    32       // candidates per actor block
#define NCHUNK 7       // ceil(201/32)

// Scratch (device globals: no allocation allowed)
__device__ float g_psum[BATCH][NCH][ND];
__device__ float g_pmax[BATCH][NCH][ND];
__device__ float g_pooled[BATCH][2 * ND];
__device__ float g_pproj[BATCH][HA];
__device__ float g_scores[BATCH][NC];
__device__ int   g_mask_i32;
// Pre-split bf16 fragment-packed actor weights: (bh0, bh1, bl0, bl1) per lane.
__device__ uint4 g_awf1[8 * 32 * 32];    // [kc 8][ntg 32][lane 32]   (k=128)
__device__ uint4 g_awf2[16 * 32 * 32];   // [kc 16][ntg 32][lane 32]  (k=256)

// ---- f32x2 packed helpers ----
static __device__ __forceinline__ unsigned long long dup2(float w) {
    unsigned long long r;
    unsigned int b = __float_as_uint(w);
    asm("mov.b64 %0, {%1, %1};" : "=l"(r) : "r"(b));
    return r;
}
static __device__ __forceinline__ unsigned long long pk2(float lo, float hi) {
    unsigned long long r;
    unsigned int a = __float_as_uint(lo), b = __float_as_uint(hi);
    asm("mov.b64 %0, {%1, %2};" : "=l"(r) : "r"(a), "r"(b));
    return r;
}
static __device__ __forceinline__ unsigned long long fma2(
    unsigned long long a, unsigned long long b, unsigned long long c) {
    unsigned long long d;
    asm("fma.rn.f32x2 %0, %1, %2, %3;" : "=l"(d) : "l"(a), "l"(b), "l"(c));
    return d;
}
static __device__ __forceinline__ void unpack2(unsigned long long v, float& lo, float& hi) {
    unsigned int a, b;
    asm("mov.b64 {%0, %1}, %2;" : "=r"(a), "=r"(b) : "l"(v));
    lo = __uint_as_float(a);
    hi = __uint_as_float(b);
}

// ---- bf16 split/pack + warp-MMA helpers (sm_80+ generic) ----
static __device__ __forceinline__ void split_bf16(float f, __nv_bfloat16& h, __nv_bfloat16& l) {
    h = __float2bfloat16_rn(f);
    l = __float2bfloat16_rn(f - __bfloat162float(h));
}
static __device__ __forceinline__ uint32_t pack_bf162(__nv_bfloat16 e0, __nv_bfloat16 e1) {
    __nv_bfloat162 v = __halves2bfloat162(e0, e1);   // .x = e0 (low 16 bits)
    return *reinterpret_cast<uint32_t*>(&v);
}
static __device__ __forceinline__ void split_pack2(float f0, float f1,
                                                   uint32_t& hp, uint32_t& lp) {
    __nv_bfloat16 h0, l0, h1, l1;
    split_bf16(f0, h0, l0);
    split_bf16(f1, h1, l1);
    hp = pack_bf162(h0, h1);
    lp = pack_bf162(l0, l1);
}
static __device__ __forceinline__ void hmma_bf16(
    float* d, const uint4& a, uint32_t b0, uint32_t b1) {
    asm volatile(
        "mma.sync.aligned.m16n8k16.row.col.f32.bf16.bf16.f32 "
        "{%0,%1,%2,%3}, {%4,%5,%6,%7}, {%8,%9}, {%0,%1,%2,%3};"
        : "+f"(d[0]), "+f"(d[1]), "+f"(d[2]), "+f"(d[3])
        : "r"(a.x), "r"(a.y), "r"(a.z), "r"(a.w), "r"(b0), "r"(b1));
}

// ---------------------------------------------------------------------------
// K0: weight pre-split (all blocks) + mask-dtype sniff (block 0, warp 0).
// ---------------------------------------------------------------------------
__global__ __launch_bounds__(256) void k_wsplit(
    const float* __restrict__ aw1, const float* __restrict__ aw2,
    const unsigned char* __restrict__ m)
{
    if (blockIdx.x == 0 && threadIdx.x < 32) {
        int any = 0;
        for (int i = threadIdx.x; i < 1024; i += 32)
            if ((i & 3) && m[i]) any = 1;
        const unsigned bal = __ballot_sync(0xffffffffu, any);
        if (threadIdx.x == 0) g_mask_i32 = bal ? 0 : 1;
    }

    const int t = blockIdx.x * 256 + threadIdx.x;
    const int n1 = 8 * 32 * 32;
    if (t < n1) {
        const int lane = t & 31, ntg = (t >> 5) & 31, kc = t >> 10;
        const int g = lane >> 2, tg = lane & 3;
        const int j = ntg * 8 + g;
        const int k0 = kc * 16 + 2 * tg;
        __nv_bfloat16 h00, l00, h01, l01, h10, l10, h11, l11;
        split_bf16(aw1[(k0 + 0) * HA + j], h00, l00);
        split_bf16(aw1[(k0 + 1) * HA + j], h01, l01);
        split_bf16(aw1[(k0 + 8) * HA + j], h10, l10);
        split_bf16(aw1[(k0 + 9) * HA + j], h11, l11);
        uint4 v;
        v.x = pack_bf162(h00, h01);
        v.y = pack_bf162(h10, h11);
        v.z = pack_bf162(l00, l01);
        v.w = pack_bf162(l10, l11);
        g_awf1[t] = v;
    } else {
        const int t2 = t - n1;
        if (t2 >= 16 * 32 * 32) return;
        const int lane = t2 & 31, ntg = (t2 >> 5) & 31, kc = t2 >> 10;
        const int g = lane >> 2, tg = lane & 3;
        const int j = ntg * 8 + g;
        const int k0 = kc * 16 + 2 * tg;
        __nv_bfloat16 h00, l00, h01, l01, h10, l10, h11, l11;
        split_bf16(aw2[(k0 + 0) * HA + j], h00, l00);
        split_bf16(aw2[(k0 + 1) * HA + j], h01, l01);
        split_bf16(aw2[(k0 + 8) * HA + j], h10, l10);
        split_bf16(aw2[(k0 + 9) * HA + j], h11, l11);
        uint4 v;
        v.x = pack_bf162(h00, h01);
        v.y = pack_bf162(h10, h11);
        v.z = pack_bf162(l00, l01);
        v.w = pack_bf162(l10, l11);
        g_awf2[t2] = v;
    }
}

// ---------------------------------------------------------------------------
// K1: featpool via 3-term bf16 split MMA (m16n8k16), full-node predication.
// Covers all NN nodes (padded to NCH*TPT*128); pooling fold guards node < NN.
// ---------------------------------------------------------------------------
__global__ __launch_bounds__(256) void k_featpool_wmma(
    const float* __restrict__ x,
    const float* __restrict__ w1, const float* __restrict__ b1,
    const float* __restrict__ w2, const float* __restrict__ b2)
{
    extern __shared__ __align__(16) uint32_t s_dyn[];
    uint32_t* s_Ah = s_dyn;            // 8mt*4kc*128 = 4096 u32 (16KB)
    uint32_t* s_Al = s_dyn + 4096;     // 16KB
    __shared__ __align__(16) float4 s_x4[128];
    __shared__ __align__(16) float s_w1t[H][4];

    const int tid = threadIdx.x;
    const int wid = tid >> 5, lane = tid & 31;
    const int b = blockIdx.y, chunk = blockIdx.x;
    const int base = chunk * TPT * 128;
    const int tig = lane & 3;
    const int gid = lane >> 2;

    if (tid < H) {
        s_w1t[tid][0] = w1[tid];
        s_w1t[tid][1] = w1[H + tid];
        s_w1t[tid][2] = w1[2 * H + tid];
        s_w1t[tid][3] = b1[tid];
    }

    // B fragments: w2[k][d] (k-major). Per (kc 4, nt 2): 2 hi + 2 lo regs.
    uint32_t Bh[4][2][2], Bl[4][2][2];
#pragma unroll
    for (int kc = 0; kc < 4; kc++)
#pragma unroll
        for (int nt = 0; nt < 2; nt++) {
            const int d = 16 * wid + nt * 8 + gid;
            const int k0 = kc * 16 + 2 * tig;
            __nv_bfloat16 h0, l0, h1, l1;
            split_bf16(__ldg(w2 + (k0 + 0) * ND + d), h0, l0);
            split_bf16(__ldg(w2 + (k0 + 1) * ND + d), h1, l1);
            Bh[kc][nt][0] = pack_bf162(h0, h1);
            Bl[kc][nt][0] = pack_bf162(l0, l1);
            split_bf16(__ldg(w2 + (k0 + 8) * ND + d), h0, l0);
            split_bf16(__ldg(w2 + (k0 + 9) * ND + d), h1, l1);
            Bh[kc][nt][1] = pack_bf162(h0, h1);
            Bl[kc][nt][1] = pack_bf162(l0, l1);
        }

    float bcol[2][2];
#pragma unroll
    for (int nt = 0; nt < 2; nt++) {
        const int d0 = 16 * wid + nt * 8 + 2 * tig;
        bcol[nt][0] = b2[d0];
        bcol[nt][1] = b2[d0 + 1];
    }

    float psum[2][4], pmax[2][4];
#pragma unroll
    for (int nt = 0; nt < 2; nt++)
#pragma unroll
        for (int e = 0; e < 4; e++) { psum[nt][e] = 0.f; pmax[nt][e] = 0.f; }

    __syncthreads();

    for (int t = 0; t < TPT; t++) {
        if (tid < 128) {
            const int node = base + t * 128 + tid;
            float4 xv = make_float4(0.f, 0.f, 0.f, 0.f);
            if (node < NN) {
                const float* xp = x + ((long)b * NN + node) * 3;
                xv.x = xp[0]; xv.y = xp[1]; xv.z = xp[2];
            }
            s_x4[tid] = xv;
        }
        __syncthreads();

        // layer-1 into bf16 A-fragment layout: 16 slots per thread.
#pragma unroll
        for (int q = 0; q < 16; q++) {
            const int s = q * 256 + tid;
            const int r = s & 3;
            const int ln = (s >> 2) & 31;
            const int kc = (s >> 7) & 3;
            const int mt = s >> 9;
            const int row = mt * 16 + (ln >> 2) + (r & 1) * 8;
            const int k0 = kc * 16 + 2 * (ln & 3) + ((r >> 1) & 1) * 8;
            const float4 xv = s_x4[row];
            const float4 wa = *(const float4*)&s_w1t[k0][0];
            const float4 wb = *(const float4*)&s_w1t[k0 + 1][0];
            const float h0 = fmaxf(fmaf(xv.x, wa.x, fmaf(xv.y, wa.y, fmaf(xv.z, wa.z, wa.w))), 0.f);
            const float h1 = fmaxf(fmaf(xv.x, wb.x, fmaf(xv.y, wb.y, fmaf(xv.z, wb.z, wb.w))), 0.f);
            uint32_t hp, lp;
            split_pack2(h0, h1, hp, lp);
            const int addr = (mt * 4 + kc) * 128 + ln * 4 + r;
            s_Ah[addr] = hp;
            s_Al[addr] = lp;
        }
        __syncthreads();

        // MMA (3-term bf16) + predicated pooling fold
        for (int mt = 0; mt < 8; mt++) {
            float d[2][4];
#pragma unroll
            for (int nt = 0; nt < 2; nt++)
#pragma unroll
                for (int e = 0; e < 4; e++) d[nt][e] = 0.f;
#pragma unroll
            for (int kc = 0; kc < 4; kc++) {
                const int off = (mt * 4 + kc) * 128 + lane * 4;
                const uint4 ah = *(const uint4*)&s_Ah[off];
                const uint4 al = *(const uint4*)&s_Al[off];
#pragma unroll
                for (int nt = 0; nt < 2; nt++) {
                    hmma_bf16(d[nt], ah, Bh[kc][nt][0], Bh[kc][nt][1]);
                    hmma_bf16(d[nt], ah, Bl[kc][nt][0], Bl[kc][nt][1]);
                    hmma_bf16(d[nt], al, Bh[kc][nt][0], Bh[kc][nt][1]);
                }
            }
            const int r0 = base + t * 128 + mt * 16 + gid;   // node of d[0], d[1]
            const bool v0 = r0 < NN;
            const bool v1 = (r0 + 8) < NN;                   // node of d[2], d[3]
#pragma unroll
            for (int nt = 0; nt < 2; nt++) {
                if (v0) {
                    const float y0 = fmaxf(d[nt][0] + bcol[nt][0], 0.f);
                    const float y1 = fmaxf(d[nt][1] + bcol[nt][1], 0.f);
                    psum[nt][0] += y0; pmax[nt][0] = fmaxf(pmax[nt][0], y0);
                    psum[nt][1] += y1; pmax[nt][1] = fmaxf(pmax[nt][1], y1);
                }
                if (v1) {
                    const float y2 = fmaxf(d[nt][2] + bcol[nt][0], 0.f);
                    const float y3 = fmaxf(d[nt][3] + bcol[nt][1], 0.f);
                    psum[nt][2] += y2; pmax[nt][2] = fmaxf(pmax[nt][2], y2);
                    psum[nt][3] += y3; pmax[nt][3] = fmaxf(pmax[nt][3], y3);
                }
            }
        }
    }

#pragma unroll
    for (int nt = 0; nt < 2; nt++) {
        float sc0 = psum[nt][0] + psum[nt][2];
        float sc1 = psum[nt][1] + psum[nt][3];
        float mc0 = fmaxf(pmax[nt][0], pmax[nt][2]);
        float mc1 = fmaxf(pmax[nt][1], pmax[nt][3]);
#pragma unroll
        for (int ofs = 4; ofs <= 16; ofs <<= 1) {
            sc0 += __shfl_xor_sync(0xffffffffu, sc0, ofs);
            sc1 += __shfl_xor_sync(0xffffffffu, sc1, ofs);
            mc0 = fmaxf(mc0, __shfl_xor_sync(0xffffffffu, mc0, ofs));
            mc1 = fmaxf(mc1, __shfl_xor_sync(0xffffffffu, mc1, ofs));
        }
        if (lane < 4) {
            const int d0 = 16 * wid + nt * 8 + 2 * lane;
            g_psum[b][chunk][d0]     = sc0;
            g_psum[b][chunk][d0 + 1] = sc1;
            g_pmax[b][chunk][d0]     = mc0;
            g_pmax[b][chunk][d0 + 1] = mc1;
        }
    }
}

// ---------------------------------------------------------------------------
// K1b: combine partials -> pooled + pproj (tail eliminated).
// ---------------------------------------------------------------------------
__global__ __launch_bounds__(HA) void k_pool(const float* __restrict__ aw1) {
    __shared__ float s_pool[2 * ND];
    const int b = blockIdx.x, tid = threadIdx.x;
    if (tid < ND) {
        float s = 0.f, m = 0.f;
#pragma unroll
        for (int ch = 0; ch < NCH; ch++) {
            s += g_psum[b][ch][tid];
            m = fmaxf(m, g_pmax[b][ch][tid]);
        }
        const float mean = s * (1.f / NN);
        g_pooled[b][tid] = mean;
        g_pooled[b][ND + tid] = m;
        s_pool[tid] = mean;
        s_pool[ND + tid] = m;
    }
    __syncthreads();
    float pc = 0.f;
    for (int i = 0; i < 2 * ND; i++)
        pc = fmaf(s_pool[i], __ldg(aw1 + (ND + i) * HA + tid), pc);
    g_pproj[b][tid] = pc;
}

// ---------------------------------------------------------------------------
// K2: actor via 3-term bf16 split MMA (R11, proven).
// ---------------------------------------------------------------------------
__global__ __launch_bounds__(256, 2) void k_actor_mma(
    const float* __restrict__ x, const int* __restrict__ cand,
    const float* __restrict__ fw1, const float* __restrict__ fb1,
    const float* __restrict__ fw2, const float* __restrict__ fb2,
    const float* __restrict__ ab1, const float* __restrict__ ab2,
    const float* __restrict__ aw3, const float* __restrict__ ab3)
{
    extern __shared__ __align__(16) uint32_t sA[];
    uint32_t* s_fA  = sA;              // 2048
    uint32_t* s_fAl = sA + 2048;       // 2048
    uint32_t* s_mA  = sA + 4096;       // 4096
    uint32_t* s_mAl = sA + 8192;       // 4096
    float* s_hT  = (float*)(sA + 12288);   // 2048 (64 k x 32 c)
    float* s_x   = s_hT + 2048;            // 96
    float* s_w1t = s_x + 96;               // 256
    float* s_red = s_w1t + 256;            // 256

    const int tid = threadIdx.x;
    const int w = tid >> 5, lane = tid & 31;
    const int gid = lane >> 2, tig = lane & 3;
    const int b = blockIdx.y;
    const int c0 = blockIdx.x * CC;
    const int nvalid = min(CC, NC - c0);

    if (tid < H) {
        s_w1t[tid * 4 + 0] = fw1[tid];
        s_w1t[tid * 4 + 1] = fw1[H + tid];
        s_w1t[tid * 4 + 2] = fw1[2 * H + tid];
        s_w1t[tid * 4 + 3] = fb1[tid];
    }
    if (tid < CC * 3) {
        const int c = tid / 3, i = tid - c * 3;
        float v = 0.f;
        if (c < nvalid) {
            const int node = cand[b * NC + c0 + c];
            v = x[((long)b * NN + node) * 3 + i];
        }
        s_x[tid] = v;
    }
    __syncthreads();

    // fe layer 1 -> s_hT[k][c]
    {
        const int n1 = tid & 31, kg = tid >> 5;
        const float x0 = s_x[n1 * 3 + 0];
        const float x1 = s_x[n1 * 3 + 1];
        const float x2 = s_x[n1 * 3 + 2];
#pragma unroll
        for (int m = 0; m < 8; m++) {
            const int k = kg * 8 + m;
            const float4 wv = *(const float4*)&s_w1t[k * 4];
            const float v = fmaf(x0, wv.x, fmaf(x1, wv.y, fmaf(x2, wv.z, wv.w)));
            s_hT[k * CC + n1] = fmaxf(v, 0.f);
        }
    }
    __syncthreads();

    // fe layer 2 -> feat fragments
    {
        const int dg = tid & 63, qh = tid >> 6;
        const int d0 = 2 * dg;
        unsigned long long a2[8];
#pragma unroll
        for (int i = 0; i < 8; i++) a2[i] = 0ull;
#pragma unroll 4
        for (int k = 0; k < H; k++) {
            const float2 wp = __ldg((const float2*)(fw2 + k * ND + d0));
            const unsigned long long wpk = pk2(wp.x, wp.y);
            const float4 hA = *(const float4*)(s_hT + k * CC + qh * 8);
            const float4 hB = *(const float4*)(s_hT + k * CC + qh * 8 + 4);
            a2[0] = fma2(dup2(hA.x), wpk, a2[0]);
            a2[1] = fma2(dup2(hA.y), wpk, a2[1]);
            a2[2] = fma2(dup2(hA.z), wpk, a2[2]);
            a2[3] = fma2(dup2(hA.w), wpk, a2[3]);
            a2[4] = fma2(dup2(hB.x), wpk, a2[4]);
            a2[5] = fma2(dup2(hB.y), wpk, a2[5]);
            a2[6] = fma2(dup2(hB.z), wpk, a2[6]);
            a2[7] = fma2(dup2(hB.w), wpk, a2[7]);
        }
        const float b20 = fb2[d0], b21 = fb2[d0 + 1];
        const int kc = d0 >> 4;
        const int t2 = (d0 >> 1) & 3;
        const int r2 = ((d0 >> 3) & 1) * 2;
#pragma unroll
        for (int i = 0; i < 8; i++) {
            const int c = qh * 8 + i;
            float lo, hi;
            unpack2(a2[i], lo, hi);
            const float y0 = fmaxf(lo + b20, 0.f);
            const float y1 = fmaxf(hi + b21, 0.f);
            uint32_t hp, lp;
            split_pack2(y0, y1, hp, lp);
            const int rit = c & 15;
            const int addr = ((c >> 4) * 8 + kc) * 128 +
                             ((rit & 7) * 4 + t2) * 4 + (rit >> 3) + r2;
            s_fA[addr] = hp;
            s_fAl[addr] = lp;
        }
    }

    float bj1[4][2], bj2v[4][2], w3j[4][2];
#pragma unroll
    for (int nt = 0; nt < 4; nt++) {
        const int j0 = (4 * w + nt) * 8 + 2 * tig;
        bj1[nt][0] = ab1[j0] + g_pproj[b][j0];
        bj1[nt][1] = ab1[j0 + 1] + g_pproj[b][j0 + 1];
        bj2v[nt][0] = ab2[j0];     bj2v[nt][1] = ab2[j0 + 1];
        w3j[nt][0] = aw3[j0];      w3j[nt][1] = aw3[j0 + 1];
    }
    __syncthreads();

    float acc[2][4][4];

    // ---- layer 1 MMA: kc = 0..7 ----
#pragma unroll
    for (int mt = 0; mt < 2; mt++)
#pragma unroll
        for (int nt = 0; nt < 4; nt++)
#pragma unroll
            for (int e = 0; e < 4; e++) acc[mt][nt][e] = 0.f;

#pragma unroll 2
    for (int kc = 0; kc < 8; kc++) {
        const uint4 ah0 = *(const uint4*)&s_fA[kc * 128 + lane * 4];
        const uint4 al0 = *(const uint4*)&s_fAl[kc * 128 + lane * 4];
        const uint4 ah1 = *(const uint4*)&s_fA[(8 + kc) * 128 + lane * 4];
        const uint4 al1 = *(const uint4*)&s_fAl[(8 + kc) * 128 + lane * 4];
#pragma unroll
        for (int nt = 0; nt < 4; nt++) {
            const uint4 bf = __ldg(&g_awf1[(kc * 32 + 4 * w + nt) * 32 + lane]);
            hmma_bf16(acc[0][nt], ah0, bf.x, bf.y);
            hmma_bf16(acc[0][nt], ah0, bf.z, bf.w);
            hmma_bf16(acc[0][nt], al0, bf.x, bf.y);
            hmma_bf16(acc[1][nt], ah1, bf.x, bf.y);
            hmma_bf16(acc[1][nt], ah1, bf.z, bf.w);
            hmma_bf16(acc[1][nt], al1, bf.x, bf.y);
        }
    }

    // layer-1 epilogue: tanh -> mid fragments
#pragma unroll
    for (int mt = 0; mt < 2; mt++)
#pragma unroll
        for (int nt = 0; nt < 4; nt++) {
            const int ntg = 4 * w + nt;
            const int kc2 = ntg >> 1;
            const int r2 = (ntg & 1) * 2;
            const int base = (mt * 16 + kc2) * 128 + (gid * 4 + tig) * 4 + r2;
            const float v0 = tanhf(acc[mt][nt][0] + bj1[nt][0]);
            const float v1 = tanhf(acc[mt][nt][1] + bj1[nt][1]);
            const float v2 = tanhf(acc[mt][nt][2] + bj1[nt][0]);
            const float v3 = tanhf(acc[mt][nt][3] + bj1[nt][1]);
            uint32_t hp, lp;
            split_pack2(v0, v1, hp, lp);
            s_mA[base] = hp;     s_mAl[base] = lp;
            split_pack2(v2, v3, hp, lp);
            s_mA[base + 1] = hp; s_mAl[base + 1] = lp;
        }
    __syncthreads();

    // ---- layer 2 MMA: kc = 0..15 ----
#pragma unroll
    for (int mt = 0; mt < 2; mt++)
#pragma unroll
        for (int nt = 0; nt < 4; nt++)
#pragma unroll
            for (int e = 0; e < 4; e++) acc[mt][nt][e] = 0.f;

#pragma unroll 2
    for (int kc = 0; kc < 16; kc++) {
        const uint4 ah0 = *(const uint4*)&s_mA[kc * 128 + lane * 4];
        const uint4 al0 = *(const uint4*)&s_mAl[kc * 128 + lane * 4];
        const uint4 ah1 = *(const uint4*)&s_mA[(16 + kc) * 128 + lane * 4];
        const uint4 al1 = *(const uint4*)&s_mAl[(16 + kc) * 128 + lane * 4];
#pragma unroll
        for (int nt = 0; nt < 4; nt++) {
            const uint4 bf = __ldg(&g_awf2[(kc * 32 + 4 * w + nt) * 32 + lane]);
            hmma_bf16(acc[0][nt], ah0, bf.x, bf.y);
            hmma_bf16(acc[0][nt], ah0, bf.z, bf.w);
            hmma_bf16(acc[0][nt], al0, bf.x, bf.y);
            hmma_bf16(acc[1][nt], ah1, bf.x, bf.y);
            hmma_bf16(acc[1][nt], ah1, bf.z, bf.w);
            hmma_bf16(acc[1][nt], al1, bf.x, bf.y);
        }
    }

    // ---- layer 3 ----
    {
        float pc[2][2] = {{0.f, 0.f}, {0.f, 0.f}};
#pragma unroll
        for (int mt = 0; mt < 2; mt++)
#pragma unroll
            for (int nt = 0; nt < 4; nt++) {
                pc[mt][0] += tanhf(acc[mt][nt][0] + bj2v[nt][0]) * w3j[nt][0]
                           + tanhf(acc[mt][nt][1] + bj2v[nt][1]) * w3j[nt][1];
                pc[mt][1] += tanhf(acc[mt][nt][2] + bj2v[nt][0]) * w3j[nt][0]
                           + tanhf(acc[mt][nt][3] + bj2v[nt][1]) * w3j[nt][1];
            }
#pragma unroll
        for (int mt = 0; mt < 2; mt++)
#pragma unroll
            for (int rh = 0; rh < 2; rh++) {
                float v = pc[mt][rh];
                v += __shfl_xor_sync(0xffffffffu, v, 1);
                v += __shfl_xor_sync(0xffffffffu, v, 2);
                pc[mt][rh] = v;
            }
        if (tig == 0) {
            s_red[w * 32 + 0 * 16 + gid]     = pc[0][0];
            s_red[w * 32 + 0 * 16 + gid + 8] = pc[0][1];
            s_red[w * 32 + 1 * 16 + gid]     = pc[1][0];
            s_red[w * 32 + 1 * 16 + gid + 8] = pc[1][1];
        }
    }
    __syncthreads();
    if (tid < CC) {
        float s = ab3[0];
#pragma unroll
        for (int ww = 0; ww < 8; ww++) s += s_red[ww * 32 + tid];
        if (tid < nvalid) g_scores[b][c0 + tid] = s;
    }
}

// ---------------------------------------------------------------------------
// K3: critic + masked softmax (proven).
// ---------------------------------------------------------------------------
__global__ __launch_bounds__(256) void k_final(
    const unsigned char* __restrict__ mask,
    const float* __restrict__ cw1, const float* __restrict__ cb1,
    const float* __restrict__ cw2, const float* __restrict__ cb2,
    const float* __restrict__ cw3, const float* __restrict__ cb3,
    float* __restrict__ out)
{
    __shared__ float s_in[HA];
    __shared__ float s_hid[HA];
    __shared__ float s_r[8];
    __shared__ float s_b0, s_b1v;

    const int tid = threadIdx.x, b = blockIdx.x;
    const int lane = tid & 31, warp = tid >> 5;

    s_in[tid] = g_pooled[b][tid];
    __syncthreads();
    float acc = cb1[tid];
    for (int i = 0; i < HA; i++) acc = fmaf(s_in[i], cw1[i * HA + tid], acc);
    s_hid[tid] = tanhf(acc);
    __syncthreads();
    acc = cb2[tid];
    for (int i = 0; i < HA; i++) acc = fmaf(s_hid[i], cw2[i * HA + tid], acc);
    {
        float p = tanhf(acc) * cw3[tid];
        p += __shfl_xor_sync(0xffffffffu, p, 16);
        p += __shfl_xor_sync(0xffffffffu, p, 8);
        p += __shfl_xor_sync(0xffffffffu, p, 4);
        p += __shfl_xor_sync(0xffffffffu, p, 2);
        p += __shfl_xor_sync(0xffffffffu, p, 1);
        if (lane == 0) s_r[warp] = p;
    }
    __syncthreads();
    if (tid == 0) {
        float v = cb3[0];
#pragma unroll
        for (int w = 0; w < 8; w++) v += s_r[w];
        out[BATCH * NC + b] = v;
    }

    const int c = tid;
    bool valid = false;
    float s = -FLT_MAX;
    if (c < NC) {
        const int mi = b * NC + c;
        const int mv = g_mask_i32 ? ((const int*)mask)[mi] : (int)mask[mi];
        valid = (mv != 0);
        if (valid) s = g_scores[b][c];
    }
    float m = s;
    m = fmaxf(m, __shfl_xor_sync(0xffffffffu, m, 16));
    m = fmaxf(m, __shfl_xor_sync(0xffffffffu, m, 8));
    m = fmaxf(m, __shfl_xor_sync(0xffffffffu, m, 4));
    m = fmaxf(m, __shfl_xor_sync(0xffffffffu, m, 2));
    m = fmaxf(m, __shfl_xor_sync(0xffffffffu, m, 1));
    __syncthreads();
    if (lane == 0) s_r[warp] = m;
    __syncthreads();
    if (warp == 0) {
        float t = (lane < 8) ? s_r[lane] : -FLT_MAX;
        t = fmaxf(t, __shfl_xor_sync(0xffffffffu, t, 4));
        t = fmaxf(t, __shfl_xor_sync(0xffffffffu, t, 2));
        t = fmaxf(t, __shfl_xor_sync(0xffffffffu, t, 1));
        if (lane == 0) s_b0 = t;
    }
    __syncthreads();
    const float mx = s_b0;
    const float e = valid ? expf(s - mx) : 0.f;
    float se = e;
    se += __shfl_xor_sync(0xffffffffu, se, 16);
    se += __shfl_xor_sync(0xffffffffu, se, 8);
    se += __shfl_xor_sync(0xffffffffu, se, 4);
    se += __shfl_xor_sync(0xffffffffu, se, 2);
    se += __shfl_xor_sync(0xffffffffu, se, 1);
    __syncthreads();
    if (lane == 0) s_r[warp] = se;
    __syncthreads();
    if (warp == 0) {
        float t = (lane < 8) ? s_r[lane] : 0.f;
        t += __shfl_xor_sync(0xffffffffu, t, 4);
        t += __shfl_xor_sync(0xffffffffu, t, 2);
        t += __shfl_xor_sync(0xffffffffu, t, 1);
        if (lane == 0) s_b1v = t;
    }
    __syncthreads();
    if (c < NC) out[b * NC + c] = e / s_b1v;
}

// ---------------------------------------------------------------------------
extern "C" void kernel_launch(void* const* d_in, const int* in_sizes, int n_in,
                              void* d_out, int out_size)
{
    const float* x    = (const float*)d_in[0];
    const int*   cand = (const int*)d_in[1];
    const unsigned char* mask = (const unsigned char*)d_in[2];
    const float* fw1 = (const float*)d_in[3];
    const float* fb1 = (const float*)d_in[4];
    const float* fw2 = (const float*)d_in[5];
    const float* fb2 = (const float*)d_in[6];
    const float* aw1 = (const float*)d_in[7];
    const float* ab1 = (const float*)d_in[8];
    const float* aw2 = (const float*)d_in[9];
    const float* ab2 = (const float*)d_in[10];
    const float* aw3 = (const float*)d_in[11];
    const float* ab3 = (const float*)d_in[12];
    const float* cw1 = (const float*)d_in[13];
    const float* cb1 = (const float*)d_in[14];
    const float* cw2 = (const float*)d_in[15];
    const float* cb2 = (const float*)d_in[16];
    const float* cw3 = (const float*)d_in[17];
    const float* cb3 = (const float*)d_in[18];
    float* out = (float*)d_out;

    const int smem_fp = 2 * 4096 * (int)sizeof(uint32_t);   // 32KB
    cudaFuncSetAttribute(k_featpool_wmma,
                         cudaFuncAttributeMaxDynamicSharedMemorySize, smem_fp);
    const int smem_actor = 14944 * (int)sizeof(uint32_t);   // 59776 B
    cudaFuncSetAttribute(k_actor_mma,
                         cudaFuncAttributeMaxDynamicSharedMemorySize, smem_actor);

    k_wsplit<<<96, 256>>>(aw1, aw2, mask);
    k_featpool_wmma<<<dim3(NCH, BATCH), 256, smem_fp>>>(x, fw1, fb1, fw2, fb2);
    k_pool<<<BATCH, HA>>>(aw1);
    k_actor_mma<<<dim3(NCHUNK, BATCH), 256, smem_actor>>>(
        x, cand, fw1, fb1, fw2, fb2, ab1, ab2, aw3, ab3);
    k_final<<<BATCH, 256>>>(mask, cw1, cb1, cw2, cb2, cw3, cb3, out);
}